// round 11
// baseline (speedup 1.0000x reference)
#include <cuda_runtime.h>
#include <cuda_bf16.h>
#include <cstdint>

typedef unsigned long long u64;
typedef uint32_t u32;

constexpr int CB = 1024;   // batch
constexpr int CF = 4096;   // feature
constexpr int CV = 20000;  // vocab
constexpr int CE = 512;    // embed dim
constexpr int CH = 1024;   // hidden
constexpr int CL = 20;     // sentence length
constexpr int CD = 4;      // distractors

// ---------------- tf32 GEMM tiling ----------------
constexpr int BM = 128, BN = 128, BK = 16;
constexpr int APAD = 24;                 // float row pitch: conflict-free LDS.64 frags
constexpr int TFL = BM * APAD;
constexpr int SMEM3 = 2 * 4 * TFL * 4;   // 98304 B
constexpr int SMEM1 = 2 * 2 * TFL * 4;   // 49152 B
// ---------------- bf16 GEMM tiling ----------------
constexpr int BKB = 32;                  // bf16 k per stage
constexpr int PADB = 48;                 // bf16 row pitch (24 words) -> conflict-free
constexpr int TBF = 128 * PADB;          // bf16 elems per tile
constexpr int SMEMB = 2 * 2 * TBF * 2;   // 49152 B

// ---------------- scratch (static device globals; no allocation) ----------------
#define DG __device__ __align__(256)
DG float g_pw_h[(size_t)CV * CH];    DG float g_pw_l[(size_t)CV * CH];
DG __nv_bfloat16 g_pw_bf[(size_t)CV * CH];
DG float g_wihs_h[4 * CH * CE];      DG float g_wihs_l[4 * CH * CE];
DG float g_whhs_h[4 * CH * CH];      DG float g_whhs_l[4 * CH * CH];
DG float g_wihr_h[4 * CH * CE];      DG float g_wihr_l[4 * CH * CE];
DG float g_whhr_h[4 * CH * CH];      DG float g_whhr_l[4 * CH * CH];
DG float g_affs_h[CH * CF];          DG float g_affs_l[CH * CF];
DG float g_affr_h[CF * CH];          DG float g_affr_l[CF * CH];
DG float g_tgt_h[(size_t)CB * CF];   DG float g_tgt_l[(size_t)CB * CF];
DG float g_dst_h[(size_t)CD * CB * CF]; DG float g_dst_l[(size_t)CD * CB * CF];
DG float g_r_h[(size_t)CB * CF];     DG float g_r_l[(size_t)CB * CF];
DG float g_hs_h[CB * CH];            DG float g_hs_l[CB * CH];
DG __nv_bfloat16 g_hs_bf[CB * CH];
DG float g_hr_h[CB * CH];            DG float g_hr_l[CB * CH];
DG float g_x_h[CB * CE];             DG float g_x_l[CB * CE];
DG float g_xr_h[CB * CE];            DG float g_xr_l[CB * CE];
DG float g_logits[(size_t)CB * CV];
DG float g_gates[(size_t)CB * 4 * CH];
DG float g_gates_r[(size_t)CB * 4 * CH];
DG float g_hs[CB * CH];
DG float g_hr[CB * CH];
DG float g_cs[CB * CH];
DG float g_cr[CB * CH];
DG float g_lp[CB];
DG float g_r[(size_t)CB * CF];
DG float g_ts[(size_t)CB * CB];
DG float g_ds[(size_t)CD * CB * CB];
DG float g_rowloss[CB];
DG float g_rowcorr[CB];
DG float g_wmax2[1];
DG int   g_msg[CL * CB];

// ---------------- low-level helpers ----------------
__device__ __forceinline__ u32 s2u(const void* p) {
    u32 a; asm("{ .reg .u64 t; cvta.to.shared.u64 t, %1; cvt.u32.u64 %0, t; }" : "=r"(a) : "l"(p));
    return a;
}
__device__ __forceinline__ float tf32r(float x) {
    float r; asm("cvt.rna.tf32.f32 %0, %1;" : "=f"(r) : "f"(x)); return r;
}
__device__ __forceinline__ void cp16(u32 dst, const void* src, bool v) {
    int sz = v ? 16 : 0;
    asm volatile("cp.async.cg.shared.global [%0], [%1], 16, %2;" :: "r"(dst), "l"(src), "r"(sz) : "memory");
}
#define CP_COMMIT() asm volatile("cp.async.commit_group;" ::: "memory")

__device__ __forceinline__ void mma8(float* d, const u32* a, const u32* b) {
    asm volatile(
        "mma.sync.aligned.m16n8k8.row.col.f32.tf32.tf32.f32 "
        "{%0,%1,%2,%3}, {%4,%5,%6,%7}, {%8,%9}, {%0,%1,%2,%3};"
        : "+f"(d[0]), "+f"(d[1]), "+f"(d[2]), "+f"(d[3])
        : "r"(a[0]), "r"(a[1]), "r"(a[2]), "r"(a[3]), "r"(b[0]), "r"(b[1]));
}
__device__ __forceinline__ void mma16(float* d, const u32* a, const u32* b) {
    asm volatile(
        "mma.sync.aligned.m16n8k16.row.col.f32.bf16.bf16.f32 "
        "{%0,%1,%2,%3}, {%4,%5,%6,%7}, {%8,%9}, {%0,%1,%2,%3};"
        : "+f"(d[0]), "+f"(d[1]), "+f"(d[2]), "+f"(d[3])
        : "r"(a[0]), "r"(a[1]), "r"(a[2]), "r"(a[3]), "r"(b[0]), "r"(b[1]));
}

// ---------------------------------------------------------------------------
// tf32 NT GEMM (pre-split planes, K-permuted LDS.64 frags). NPASS=3 or 1.
// ---------------------------------------------------------------------------
template<int NPASS>
__global__ __launch_bounds__(256, 2)
void tmma_nt(int M, int N,
             const float* __restrict__ A1h, const float* __restrict__ A1l, int K1,
             const float* __restrict__ A2h, const float* __restrict__ A2l, int K2,
             const float* __restrict__ B1h, const float* __restrict__ B1l,
             const float* __restrict__ B2h, const float* __restrict__ B2l,
             const float* __restrict__ bias1, const float* __restrict__ bias2,
             float* __restrict__ C)
{
    extern __shared__ float sm[];
    constexpr int PL = (NPASS == 3) ? 4 : 2;
    constexpr int OAH = 0, OAL = TFL, OBH = (NPASS == 3 ? 2 : 1) * TFL, OBL = 3 * TFL;

    const int tid  = threadIdx.x;
    const int wid  = tid >> 5;
    const int lane = tid & 31;
    const int g    = lane >> 2;
    const int t    = lane & 3;
    const int wm   = (wid & 3) * 32;
    const int wn   = (wid >> 2) * 64;
    const int bn0  = blockIdx.x * BN;
    const int bm0  = blockIdx.y * BM;

    const int nk1 = K1 / BK;
    const int nk2 = A2h ? (K2 / BK) : 0;
    const int nkt = nk1 + nk2;

    auto load_stage = [&](int gkt, int stage) {
        const float *Ah, *Al, *Bh, *Bl; int K, kt;
        if (gkt < nk1) { Ah = A1h; Al = A1l; Bh = B1h; Bl = B1l; K = K1; kt = gkt; }
        else           { Ah = A2h; Al = A2l; Bh = B2h; Bl = B2l; K = K2; kt = gkt - nk1; }
        const int koff = kt * BK;
        float* st = sm + stage * PL * TFL;
        u32 uah = s2u(st + OAH), ubh = s2u(st + OBH);
        u32 ual = s2u(st + OAL), ubl = s2u(st + OBL);
#pragma unroll
        for (int it = 0; it < 2; it++) {
            int c = tid + it * 256;
            int row = c >> 2, ch = c & 3;
            u32 off = (u32)(row * APAD + ch * 4) * 4;
            const size_t ga = (size_t)(bm0 + row) * K + koff + ch * 4;
            cp16(uah + off, Ah + ga, true);
            if (NPASS == 3) cp16(ual + off, Al + ga, true);
            bool v = (bn0 + row) < N;
            const size_t gb = (size_t)(v ? (bn0 + row) : 0) * K + koff + ch * 4;
            cp16(ubh + off, Bh + gb, v);
            if (NPASS == 3) cp16(ubl + off, Bl + gb, v);
        }
        CP_COMMIT();
    };

    float d[2][8][4];
#pragma unroll
    for (int i = 0; i < 2; i++)
#pragma unroll
        for (int j = 0; j < 8; j++)
#pragma unroll
            for (int q = 0; q < 4; q++) d[i][j][q] = 0.f;

    load_stage(0, 0);

    for (int s = 0; s < nkt; s++) {
        if (s + 1 < nkt) {
            load_stage(s + 1, (s + 1) & 1);
            asm volatile("cp.async.wait_group 1;" ::: "memory");
        } else {
            asm volatile("cp.async.wait_group 0;" ::: "memory");
        }
        __syncthreads();

        const float* st  = sm + (s & 1) * PL * TFL;
        const float* pAh = st + OAH;
        const float* pAl = st + OAL;
        const float* pBh = st + OBH;
        const float* pBl = st + OBL;

#pragma unroll
        for (int kk = 0; kk < BK; kk += 8) {
            float2 aH[2][2], aL[2][2];
#pragma unroll
            for (int mt = 0; mt < 2; mt++) {
                const int base = (wm + mt * 16 + g) * APAD + kk + 2 * t;
                aH[mt][0] = *(const float2*)(pAh + base);
                aH[mt][1] = *(const float2*)(pAh + base + 8 * APAD);
                if (NPASS == 3) {
                    aL[mt][0] = *(const float2*)(pAl + base);
                    aL[mt][1] = *(const float2*)(pAl + base + 8 * APAD);
                }
            }
#pragma unroll
            for (int nt = 0; nt < 8; nt++) {
                const int bidx = (wn + nt * 8 + g) * APAD + kk + 2 * t;
                float2 bHf = *(const float2*)(pBh + bidx);
                u32 bH[2] = {__float_as_uint(bHf.x), __float_as_uint(bHf.y)};
                u32 bL[2];
                if (NPASS == 3) {
                    float2 bLf = *(const float2*)(pBl + bidx);
                    bL[0] = __float_as_uint(bLf.x); bL[1] = __float_as_uint(bLf.y);
                }
#pragma unroll
                for (int mt = 0; mt < 2; mt++) {
                    u32 aH4[4] = {__float_as_uint(aH[mt][0].x), __float_as_uint(aH[mt][1].x),
                                  __float_as_uint(aH[mt][0].y), __float_as_uint(aH[mt][1].y)};
                    mma8(d[mt][nt], aH4, bH);
                    if (NPASS == 3) {
                        mma8(d[mt][nt], aH4, bL);
                        u32 aL4[4] = {__float_as_uint(aL[mt][0].x), __float_as_uint(aL[mt][1].x),
                                      __float_as_uint(aL[mt][0].y), __float_as_uint(aL[mt][1].y)};
                        mma8(d[mt][nt], aL4, bH);
                    }
                }
            }
        }
        __syncthreads();
    }

#pragma unroll
    for (int nt = 0; nt < 8; nt++) {
        const int cb = bn0 + wn + nt * 8;
        if (cb >= N) continue;
        const int col = cb + 2 * t;
        float b0 = 0.f, b1 = 0.f;
        if (bias1) { b0 += bias1[col]; b1 += bias1[col + 1]; }
        if (bias2) { b0 += bias2[col]; b1 += bias2[col + 1]; }
#pragma unroll
        for (int mt = 0; mt < 2; mt++) {
            const int row = bm0 + wm + mt * 16 + g;
            float2 v0 = make_float2(d[mt][nt][0] + b0, d[mt][nt][1] + b1);
            float2 v1 = make_float2(d[mt][nt][2] + b0, d[mt][nt][3] + b1);
            *(float2*)(C + (size_t)row * N + col) = v0;
            *(float2*)(C + (size_t)(row + 8) * N + col) = v1;
        }
    }
}

// ---------------------------------------------------------------------------
// bf16 NT GEMM: C = A*B^T + bias. Single pass (argmax phase-1 only).
// K-permutation: thread t's k16 slots <- contiguous bf16 cols 4t..4t+3.
// ---------------------------------------------------------------------------
__global__ __launch_bounds__(256, 2)
void bmma_nt(int M, int N,
             const __nv_bfloat16* __restrict__ A, int K,
             const __nv_bfloat16* __restrict__ B,
             const float* __restrict__ bias,
             float* __restrict__ C)
{
    extern __shared__ __nv_bfloat16 smb[];
    __nv_bfloat16* sA = smb;              // [2][128][PADB]
    __nv_bfloat16* sB = smb + 2 * TBF;

    const int tid  = threadIdx.x;
    const int wid  = tid >> 5;
    const int lane = tid & 31;
    const int g    = lane >> 2;
    const int t    = lane & 3;
    const int wm   = (wid & 3) * 32;
    const int wn   = (wid >> 2) * 64;
    const int bn0  = blockIdx.x * BN;
    const int bm0  = blockIdx.y * BM;

    const int nkt = K / BKB;

    auto load_stage = [&](int kt, int stage) {
        const int koff = kt * BKB;
        u32 ua = s2u(sA + stage * TBF), ub = s2u(sB + stage * TBF);
#pragma unroll
        for (int it = 0; it < 2; it++) {
            int c = tid + it * 256;          // 512 = 128 rows x 4 16B-chunks
            int row = c >> 2, ch = c & 3;
            u32 off = (u32)(row * PADB + ch * 8) * 2;
            cp16(ua + off, A + (size_t)(bm0 + row) * K + koff + ch * 8, true);
            bool v = (bn0 + row) < N;
            cp16(ub + off, B + (size_t)(v ? (bn0 + row) : 0) * K + koff + ch * 8, v);
        }
        CP_COMMIT();
    };

    float d[2][8][4];
#pragma unroll
    for (int i = 0; i < 2; i++)
#pragma unroll
        for (int j = 0; j < 8; j++)
#pragma unroll
            for (int q = 0; q < 4; q++) d[i][j][q] = 0.f;

    load_stage(0, 0);

    for (int s = 0; s < nkt; s++) {
        if (s + 1 < nkt) {
            load_stage(s + 1, (s + 1) & 1);
            asm volatile("cp.async.wait_group 1;" ::: "memory");
        } else {
            asm volatile("cp.async.wait_group 0;" ::: "memory");
        }
        __syncthreads();

        const __nv_bfloat16* pA = sA + (s & 1) * TBF;
        const __nv_bfloat16* pB = sB + (s & 1) * TBF;

#pragma unroll
        for (int kk = 0; kk < BKB; kk += 16) {
            uint2 a[2][2];
#pragma unroll
            for (int mt = 0; mt < 2; mt++) {
                const int base = (wm + mt * 16 + g) * PADB + kk + 4 * t;
                a[mt][0] = *(const uint2*)(pA + base);
                a[mt][1] = *(const uint2*)(pA + base + 8 * PADB);
            }
#pragma unroll
            for (int nt = 0; nt < 8; nt++) {
                uint2 bb = *(const uint2*)(pB + (wn + nt * 8 + g) * PADB + kk + 4 * t);
                u32 bfr[2] = {bb.x, bb.y};
#pragma unroll
                for (int mt = 0; mt < 2; mt++) {
                    u32 af[4] = {a[mt][0].x, a[mt][1].x, a[mt][0].y, a[mt][1].y};
                    mma16(d[mt][nt], af, bfr);
                }
            }
        }
        __syncthreads();
    }

#pragma unroll
    for (int nt = 0; nt < 8; nt++) {
        const int cb = bn0 + wn + nt * 8;
        if (cb >= N) continue;
        const int col = cb + 2 * t;
        float b0 = bias ? bias[col] : 0.f;
        float b1 = bias ? bias[col + 1] : 0.f;
#pragma unroll
        for (int mt = 0; mt < 2; mt++) {
            const int row = bm0 + wm + mt * 16 + g;
            float2 v0 = make_float2(d[mt][nt][0] + b0, d[mt][nt][1] + b1);
            float2 v1 = make_float2(d[mt][nt][2] + b0, d[mt][nt][3] + b1);
            *(float2*)(C + (size_t)row * N + col) = v0;
            *(float2*)(C + (size_t)(row + 8) * N + col) = v1;
        }
    }
}

// ---------------- fused prepass ----------------
struct PJ { const float4* s; float4* h; float4* l; };
struct PrepArgs {
    PJ j[9];
    __nv_bfloat162* pwbf;   // bf16 plane for job 0 (probs_W)
    float4* z[4];           // cs, cr, hrh, hrl
    float* wmax2;
};
constexpr size_t N4_PW   = (size_t)CV * CH / 4;
constexpr size_t N4_WIH  = (size_t)CH * CE;        // 4*CH*CE/4
constexpr size_t N4_WHH  = (size_t)CH * CH;        // 4*CH*CH/4
constexpr size_t N4_AFF  = (size_t)CH * CF / 4;
constexpr size_t N4_TGT  = (size_t)CB * CF / 4;
constexpr size_t N4_DST  = (size_t)CD * CB * CF / 4;
constexpr size_t N4_Z    = (size_t)CB * CH / 4;
constexpr size_t SPLIT_TOT = N4_PW + 2 * N4_WIH + 2 * N4_WHH + 2 * N4_AFF + N4_TGT + N4_DST;
constexpr size_t PREP_TOT = SPLIT_TOT + 4 * N4_Z;

__global__ void prep_all(PrepArgs a)
{
    // device-local copy of the job-size table (host constexpr arrays are not
    // visible in device code)
    constexpr size_t JS[9] = {N4_PW, N4_WIH, N4_WHH, N4_WIH, N4_WHH, N4_AFF, N4_AFF, N4_TGT, N4_DST};

    if (blockIdx.x == 0 && threadIdx.x == 0) a.wmax2[0] = 0.f;
    const size_t stride = (size_t)gridDim.x * blockDim.x;
    for (size_t i = (size_t)blockIdx.x * blockDim.x + threadIdx.x; i < PREP_TOT; i += stride) {
        if (i >= SPLIT_TOT) {
            size_t r = i - SPLIT_TOT;
            a.z[r / N4_Z][r % N4_Z] = make_float4(0.f, 0.f, 0.f, 0.f);
            continue;
        }
        size_t r = i;
        int job = 0;
#pragma unroll
        for (int q = 0; q < 8; q++) {
            if (r >= JS[q] && job == q) { r -= JS[q]; job = q + 1; }
        }
        float4 s = a.j[job].s[r];
        float4 h, l;
        h.x = tf32r(s.x); l.x = tf32r(s.x - h.x);
        h.y = tf32r(s.y); l.y = tf32r(s.y - h.y);
        h.z = tf32r(s.z); l.z = tf32r(s.z - h.z);
        h.w = tf32r(s.w); l.w = tf32r(s.w - h.w);
        a.j[job].h[r] = h; a.j[job].l[r] = l;
        if (job == 0) {
            a.pwbf[2 * r]     = __floats2bfloat162_rn(s.x, s.y);
            a.pwbf[2 * r + 1] = __floats2bfloat162_rn(s.z, s.w);
        }
    }
}

// ---------------- elementwise kernels ----------------
__global__ void split_k(const float4* __restrict__ src, float4* __restrict__ hi,
                        float4* __restrict__ lo, int n4)
{
    int i = blockIdx.x * blockDim.x + threadIdx.x;
    if (i >= n4) return;
    float4 s = src[i];
    float4 h, l;
    h.x = tf32r(s.x); l.x = tf32r(s.x - h.x);
    h.y = tf32r(s.y); l.y = tf32r(s.y - h.y);
    h.z = tf32r(s.z); l.z = tf32r(s.z - h.z);
    h.w = tf32r(s.w); l.w = tf32r(s.w - h.w);
    hi[i] = h; lo[i] = l;
}

__global__ void gather_split_k(const int* __restrict__ tok, const int* __restrict__ sidx,
                               const float* __restrict__ emb,
                               float* __restrict__ xh, float* __restrict__ xl)
{
    int i = blockIdx.x * blockDim.x + threadIdx.x;
    if (i >= CB * (CE / 4)) return;
    int b = i / (CE / 4), j = (i % (CE / 4)) * 4;
    int tk = tok ? tok[b] : sidx[0];
    float4 e = *(const float4*)(emb + (size_t)tk * CE + j);
    float4 h, l;
    h.x = tf32r(e.x); l.x = tf32r(e.x - h.x);
    h.y = tf32r(e.y); l.y = tf32r(e.y - h.y);
    h.z = tf32r(e.z); l.z = tf32r(e.z - h.z);
    h.w = tf32r(e.w); l.w = tf32r(e.w - h.w);
    *(float4*)(xh + (size_t)b * CE + j) = h;
    *(float4*)(xl + (size_t)b * CE + j) = l;
}

__global__ void lstm_cell_split(const float* __restrict__ gates, float* __restrict__ c,
                                float* __restrict__ hraw,
                                float* __restrict__ hhi, float* __restrict__ hlo,
                                __nv_bfloat16* __restrict__ hbf)
{
    const int t = blockIdx.x * blockDim.x + threadIdx.x;
    if (t >= CB * CH) return;
    const int b = t >> 10, j = t & 1023;
    const float* g = gates + (size_t)b * (4 * CH);
    const float gi = g[j], gf = g[CH + j], gg = g[2 * CH + j], go = g[3 * CH + j];
    const float ig = 1.f / (1.f + __expf(-gi));
    const float fg = 1.f / (1.f + __expf(-gf));
    const float og = 1.f / (1.f + __expf(-go));
    const float cn = fg * c[t] + ig * tanhf(gg);
    c[t] = cn;
    const float h = og * tanhf(cn);
    hraw[t] = h;
    const float hh = tf32r(h);
    hhi[t] = hh;
    hlo[t] = tf32r(h - hh);
    if (hbf) hbf[t] = __float2bfloat16(h);
}

// max squared row-norm of probs_W
__global__ void wnorms_max(const float* __restrict__ W, float* __restrict__ wmax2)
{
    const int row = blockIdx.x * 8 + (threadIdx.x >> 5);
    const int lane = threadIdx.x & 31;
    if (row >= CV) return;
    const float* w = W + (size_t)row * CH;
    float s = 0.f;
    for (int k = lane; k < CH; k += 32) { float v = w[k]; s += v * v; }
#pragma unroll
    for (int st = 16; st > 0; st >>= 1) s += __shfl_xor_sync(0xffffffff, s, st);
    if (lane == 0) atomicMax((int*)wmax2, __float_as_int(s));
}

// argmax over approx phase-1 logits + exact fp32 rescue (margin = 2^mshift * ||h||*wmax)
__global__ void logits_argmax(const float* __restrict__ logits,
                              const float* __restrict__ h,
                              const float* __restrict__ W,
                              const float* __restrict__ pb,
                              const float* __restrict__ wmax2,
                              int* __restrict__ tok, float* __restrict__ lp,
                              int want_lp, int mshift)
{
    const int b = blockIdx.x;
    const int tid = threadIdx.x;
    __shared__ float sh[CH];
    __shared__ float smx[256], ssm[256];
    __shared__ int   sidx[256];

    float nrm = 0.f;
    for (int i = tid; i < CH; i += 256) { float v = h[(size_t)b * CH + i]; sh[i] = v; nrm += v * v; }
    smx[tid] = nrm;
    __syncthreads();
    for (int st = 128; st > 0; st >>= 1) {
        if (tid < st) smx[tid] += smx[tid + st];
        __syncthreads();
    }
    const float hn2 = smx[0];
    __syncthreads();

    const float4* row4 = (const float4*)(logits + (size_t)b * CV);
    float m = -3.4e38f, s = 0.f;
    for (int j4 = tid; j4 < CV / 4; j4 += 256) {
        float4 v = row4[j4];
        float xs[4] = {v.x, v.y, v.z, v.w};
#pragma unroll
        for (int c = 0; c < 4; c++) {
            float x = xs[c];
            if (x > m) {
                if (want_lp) s = s * expf(m - x) + 1.f;
                m = x;
            } else if (want_lp) {
                s += expf(x - m);
            }
        }
    }
    smx[tid] = m; ssm[tid] = s;
    __syncthreads();
    for (int st = 128; st > 0; st >>= 1) {
        if (tid < st) {
            float m1 = smx[tid], s1 = ssm[tid];
            float m2 = smx[tid + st], s2 = ssm[tid + st];
            if (m2 > m1) { smx[tid] = m2; ssm[tid] = s2 + s1 * expf(m1 - m2); }
            else         { ssm[tid] = s1 + s2 * expf(m2 - m1); }
        }
        __syncthreads();
    }
    const float mall = smx[0];
    const float sall = ssm[0];
    __syncthreads();

    const float margin = ldexpf(sqrtf(hn2 * wmax2[0]), mshift);
    const float thr = mall - margin;

    const float* row = logits + (size_t)b * CV;
    float bv = -3.4e38f; int bi = 0x7fffffff;
    for (int j = tid; j < CV; j += 256) {
        if (row[j] >= thr) {
            const float* w = W + (size_t)j * CH;
            float dot = pb[j];
#pragma unroll 4
            for (int k = 0; k < CH; k++) dot = fmaf(sh[k], w[k], dot);
            if (dot > bv || (dot == bv && j < bi)) { bv = dot; bi = j; }
        }
    }
    smx[tid] = bv; sidx[tid] = bi;
    __syncthreads();
    for (int st = 128; st > 0; st >>= 1) {
        if (tid < st) {
            float v2 = smx[tid + st]; int i2 = sidx[tid + st];
            if (v2 > smx[tid] || (v2 == smx[tid] && i2 < sidx[tid])) { smx[tid] = v2; sidx[tid] = i2; }
        }
        __syncthreads();
    }
    if (tid == 0) {
        tok[b] = sidx[0];
        if (want_lp) lp[b] = smx[0] - (mall + logf(sall));
    }
}

// ---------------- hinge loss / accuracy reductions ----------------
__global__ void score_rows(const float* __restrict__ ts, const float* __restrict__ ds,
                           const float* __restrict__ lp,
                           float* __restrict__ rowloss, float* __restrict__ rowcorr)
{
    const int i = blockIdx.x;
    const float* trow = ts + (size_t)i * CB;
    const float* dr0 = ds + 0ULL * CB * CB + (size_t)i * CB;
    const float* dr1 = ds + 1ULL * CB * CB + (size_t)i * CB;
    const float* dr2 = ds + 2ULL * CB * CB + (size_t)i * CB;
    const float* dr3 = ds + 3ULL * CB * CB + (size_t)i * CB;

    float ls = 0.f, et = 0.f, e0 = 0.f, e1 = 0.f, e2 = 0.f, e3 = 0.f;
    for (int j = threadIdx.x; j < CB; j += 256) {
        const float t  = trow[j];
        const float a0 = dr0[j], a1 = dr1[j], a2 = dr2[j], a3 = dr3[j];
        float h = fmaxf(0.f, 1.f - t + a0) + fmaxf(0.f, 1.f - t + a1)
                + fmaxf(0.f, 1.f - t + a2) + fmaxf(0.f, 1.f - t + a3);
        ls += h * lp[j];
        et += expf(t); e0 += expf(a0); e1 += expf(a1); e2 += expf(a2); e3 += expf(a3);
    }
    __shared__ float red[6][256];
    red[0][threadIdx.x] = ls; red[1][threadIdx.x] = et;
    red[2][threadIdx.x] = e0; red[3][threadIdx.x] = e1;
    red[4][threadIdx.x] = e2; red[5][threadIdx.x] = e3;
    __syncthreads();
    for (int st = 128; st > 0; st >>= 1) {
        if (threadIdx.x < st)
#pragma unroll
            for (int q = 0; q < 6; q++) red[q][threadIdx.x] += red[q][threadIdx.x + st];
        __syncthreads();
    }
    if (threadIdx.x == 0) {
        rowloss[i] = red[0][0];
        const float tp = red[1][0] / (float)CB;
        const float mx = fmaxf(fmaxf(red[2][0], red[3][0]), fmaxf(red[4][0], red[5][0])) / (float)CB;
        rowcorr[i] = (tp >= mx) ? 1.f : 0.f;
    }
}

__global__ void final_reduce(const float* __restrict__ rowloss,
                             const float* __restrict__ rowcorr, float* __restrict__ out)
{
    __shared__ float s1[256], s2[256];
    float a = 0.f, b = 0.f;
    for (int i = threadIdx.x; i < CB; i += 256) { a += rowloss[i]; b += rowcorr[i]; }
    s1[threadIdx.x] = a; s2[threadIdx.x] = b;
    __syncthreads();
    for (int st = 128; st > 0; st >>= 1) {
        if (threadIdx.x < st) { s1[threadIdx.x] += s1[threadIdx.x + st]; s2[threadIdx.x] += s2[threadIdx.x + st]; }
        __syncthreads();
    }
    if (threadIdx.x == 0) {
        out[0] = -s1[0] / (float)((size_t)CB * CB);
        out[1] =  s2[0] / (float)CB;
    }
}

// ---------------------------------------------------------------------------
static inline void run_split(const float* src, float* hi, float* lo, size_t n)
{
    int n4 = (int)(n / 4);
    split_k<<<(n4 + 255) / 256, 256>>>((const float4*)src, (float4*)hi, (float4*)lo, n4);
}

extern "C" void kernel_launch(void* const* d_in, const int* in_sizes, int n_in,
                              void* d_out, int out_size)
{
    (void)in_sizes; (void)n_in; (void)out_size;
    const float* target   = (const float*)d_in[0];
    const float* distract = (const float*)d_in[1];
    const int*   sidx     = (const int*)d_in[2];
    const float* emb_s   = (const float*)d_in[4];
    const float* Wih_s   = (const float*)d_in[5];
    const float* Whh_s   = (const float*)d_in[6];
    const float* bih_s   = (const float*)d_in[7];
    const float* bhh_s   = (const float*)d_in[8];
    const float* aff_s_W = (const float*)d_in[9];
    const float* aff_s_b = (const float*)d_in[10];
    const float* probs_W = (const float*)d_in[11];
    const float* probs_b = (const float*)d_in[12];
    const float* emb_r   = (const float*)d_in[13];
    const float* Wih_r   = (const float*)d_in[14];
    const float* Whh_r   = (const float*)d_in[15];
    const float* bih_r   = (const float*)d_in[16];
    const float* bhh_r   = (const float*)d_in[17];
    const float* aff_r_W = (const float*)d_in[18];
    const float* aff_r_b = (const float*)d_in[19];
    float* out = (float*)d_out;

    static cudaStream_t s2 = nullptr;
    static cudaEvent_t evFork = nullptr, evJoin = nullptr, evTok[CL];
    if (!s2) {
        cudaStreamCreateWithFlags(&s2, cudaStreamNonBlocking);
        cudaEventCreateWithFlags(&evFork, cudaEventDisableTiming);
        cudaEventCreateWithFlags(&evJoin, cudaEventDisableTiming);
        for (int t = 0; t < CL; t++) cudaEventCreateWithFlags(&evTok[t], cudaEventDisableTiming);
    }

    cudaFuncSetAttribute(tmma_nt<3>, cudaFuncAttributeMaxDynamicSharedMemorySize, SMEM3);
    cudaFuncSetAttribute(tmma_nt<1>, cudaFuncAttributeMaxDynamicSharedMemorySize, SMEM1);
    cudaFuncSetAttribute(bmma_nt,    cudaFuncAttributeMaxDynamicSharedMemorySize, SMEMB);

#define SYM(T, p, s) T* p; cudaGetSymbolAddress((void**)&p, s)
    SYM(float, pwh, g_pw_h); SYM(float, pwl, g_pw_l);
    SYM(__nv_bfloat16, pwbf, g_pw_bf);
    SYM(float, wihsh, g_wihs_h); SYM(float, wihsl, g_wihs_l);
    SYM(float, whhsh, g_whhs_h); SYM(float, whhsl, g_whhs_l);
    SYM(float, wihrh, g_wihr_h); SYM(float, wihrl, g_wihr_l);
    SYM(float, whhrh, g_whhr_h); SYM(float, whhrl, g_whhr_l);
    SYM(float, affsh, g_affs_h); SYM(float, affsl, g_affs_l);
    SYM(float, affrh, g_affr_h); SYM(float, affrl, g_affr_l);
    SYM(float, tgth, g_tgt_h);   SYM(float, tgtl, g_tgt_l);
    SYM(float, dsth, g_dst_h);   SYM(float, dstl, g_dst_l);
    SYM(float, rh, g_r_h);       SYM(float, rl, g_r_l);
    SYM(float, hsh, g_hs_h);     SYM(float, hsl, g_hs_l);
    SYM(__nv_bfloat16, hsbf, g_hs_bf);
    SYM(float, hrh, g_hr_h);     SYM(float, hrl, g_hr_l);
    SYM(float, xh, g_x_h);       SYM(float, xl, g_x_l);
    SYM(float, xrh, g_xr_h);     SYM(float, xrl, g_xr_l);
    SYM(float, p_logits, g_logits); SYM(float, p_gates, g_gates); SYM(float, p_gates_r, g_gates_r);
    SYM(float, p_hs, g_hs); SYM(float, p_hr, g_hr); SYM(float, p_cs, g_cs); SYM(float, p_cr, g_cr);
    SYM(float, p_lp, g_lp); SYM(float, p_r, g_r); SYM(float, p_ts, g_ts); SYM(float, p_ds, g_ds);
    SYM(float, p_rowloss, g_rowloss); SYM(float, p_rowcorr, g_rowcorr);
    SYM(float, p_wmax2, g_wmax2);
    SYM(int, p_msg, g_msg);
#undef SYM

    // ---- launch 1: fused prepass (splits + bf16 plane + zeros + wmax2 init) ----
    PrepArgs pa;
    pa.j[0] = {(const float4*)probs_W,  (float4*)pwh,   (float4*)pwl};
    pa.j[1] = {(const float4*)Wih_s,    (float4*)wihsh, (float4*)wihsl};
    pa.j[2] = {(const float4*)Whh_s,    (float4*)whhsh, (float4*)whhsl};
    pa.j[3] = {(const float4*)Wih_r,    (float4*)wihrh, (float4*)wihrl};
    pa.j[4] = {(const float4*)Whh_r,    (float4*)whhrh, (float4*)whhrl};
    pa.j[5] = {(const float4*)aff_s_W,  (float4*)affsh, (float4*)affsl};
    pa.j[6] = {(const float4*)aff_r_W,  (float4*)affrh, (float4*)affrl};
    pa.j[7] = {(const float4*)target,   (float4*)tgth,  (float4*)tgtl};
    pa.j[8] = {(const float4*)distract, (float4*)dsth,  (float4*)dstl};
    pa.pwbf = (__nv_bfloat162*)pwbf;
    pa.z[0] = (float4*)p_cs; pa.z[1] = (float4*)p_cr;
    pa.z[2] = (float4*)hrh;  pa.z[3] = (float4*)hrl;
    pa.wmax2 = p_wmax2;
    prep_all<<<2048, 256>>>(pa);

    // launch 2
    wnorms_max<<<(CV + 7) / 8, 256>>>(probs_W, p_wmax2);

    cudaEventRecord(evFork, 0);
    cudaStreamWaitEvent(s2, evFork, 0);

    // launch 3: h0 = target @ aff_s_W^T + aff_s_b
    tmma_nt<3><<<dim3(CH / BN, CB / BM), 256, SMEM3>>>(CB, CH,
        tgth, tgtl, CF, nullptr, nullptr, 0,
        affsh, affsl, nullptr, nullptr, aff_s_b, nullptr, p_hs);
    // launch 4
    run_split(p_hs, hsh, hsl, (size_t)CB * CH);

    // ---- sender (stream 0): launch 5 = gather, launch 6 = gates GEMM (ncu target) ----
    for (int t = 0; t < CL; t++) {
        const int* tokidx = (t == 0) ? nullptr : (p_msg + (t - 1) * CB);
        gather_split_k<<<(CB * CE / 4 + 255) / 256, 256>>>(tokidx, sidx, emb_s, xh, xl);
        tmma_nt<3><<<dim3(4 * CH / BN, CB / BM), 256, SMEM3>>>(CB, 4 * CH,
            xh, xl, CE, hsh, hsl, CH,
            wihsh, wihsl, whhsh, whhsl, bih_s, bhh_s, p_gates);
        lstm_cell_split<<<(CB * CH) / 256, 256>>>(p_gates, p_cs, p_hs, hsh, hsl, hsbf);
        if (t < CL - 1) {
            // bf16 phase-1 logits (argmax only; exact rescue below)
            bmma_nt<<<dim3((CV + BN - 1) / BN, CB / BM), 256, SMEMB>>>(CB, CV,
                hsbf, CH, pwbf, probs_b, p_logits);
            logits_argmax<<<CB, 256>>>(p_logits, p_hs, probs_W, probs_b, p_wmax2,
                                       p_msg + t * CB, p_lp, 0, -6);
        } else {
            // last step needs lp: tf32 phase-1 for accurate logsumexp
            tmma_nt<1><<<dim3((CV + BN - 1) / BN, CB / BM), 256, SMEM1>>>(CB, CV,
                hsh, nullptr, CH, nullptr, nullptr, 0,
                pwh, nullptr, nullptr, nullptr, probs_b, nullptr, p_logits);
            logits_argmax<<<CB, 256>>>(p_logits, p_hs, probs_W, probs_b, p_wmax2,
                                       p_msg + t * CB, p_lp, 1, -8);
        }
        cudaEventRecord(evTok[t], 0);
    }

    // ---- receiver (stream s2, overlapped) ----
    for (int t = 0; t < CL; t++) {
        cudaStreamWaitEvent(s2, evTok[t], 0);
        gather_split_k<<<(CB * CE / 4 + 255) / 256, 256, 0, s2>>>(p_msg + t * CB, sidx, emb_r, xrh, xrl);
        tmma_nt<3><<<dim3(4 * CH / BN, CB / BM), 256, SMEM3, s2>>>(CB, 4 * CH,
            xrh, xrl, CE, hrh, hrl, CH,
            wihrh, wihrl, whhrh, whhrl, bih_r, bhh_r, p_gates_r);
        lstm_cell_split<<<(CB * CH) / 256, 256, 0, s2>>>(p_gates_r, p_cr, p_hr, hrh, hrl, nullptr);
    }
    cudaEventRecord(evJoin, s2);
    cudaStreamWaitEvent(0, evJoin, 0);

    // r = hr @ aff_r_W^T + aff_r_b
    tmma_nt<3><<<dim3(CF / BN, CB / BM), 256, SMEM3>>>(CB, CF,
        hrh, hrl, CH, nullptr, nullptr, 0,
        affrh, affrl, nullptr, nullptr, aff_r_b, nullptr, p_r);
    run_split(p_r, rh, rl, (size_t)CB * CF);

    // ts = target @ r^T ; ds = distractors @ r^T
    tmma_nt<3><<<dim3(CB / BN, CB / BM), 256, SMEM3>>>(CB, CB,
        tgth, tgtl, CF, nullptr, nullptr, 0,
        rh, rl, nullptr, nullptr, nullptr, nullptr, p_ts);
    tmma_nt<3><<<dim3(CB / BN, (CD * CB) / BM), 256, SMEM3>>>(CD * CB, CB,
        dsth, dstl, CF, nullptr, nullptr, 0,
        rh, rl, nullptr, nullptr, nullptr, nullptr, p_ds);

    score_rows<<<CB, 256>>>(p_ts, p_ds, p_lp, p_rowloss, p_rowcorr);
    final_reduce<<<1, 256>>>(p_rowloss, p_rowcorr, out);
}

// round 13
// speedup vs baseline: 1.0355x; 1.0355x over previous
#include <cuda_runtime.h>
#include <cstdint>

typedef unsigned long long u64;
typedef uint32_t u32;

constexpr int CB = 1024;   // batch
constexpr int CF = 4096;   // feature
constexpr int CV = 20000;  // vocab
constexpr int CE = 512;    // embed dim
constexpr int CH = 1024;   // hidden
constexpr int CL = 20;     // sentence length
constexpr int CD = 4;      // distractors

// ---------------- tf32 GEMM tiling ----------------
constexpr int BM = 128, BN = 128, BK = 16;
constexpr int APAD = 24;                 // float row pitch: conflict-free LDS.64 frags
constexpr int TFL = BM * APAD;
constexpr int SMEM3 = 2 * 4 * TFL * 4;   // 98304 B
constexpr int SMEM1 = 2 * 2 * TFL * 4;   // 49152 B

// ---------------- scratch (static device globals; no allocation) ----------------
#define DG __device__ __align__(256)
DG float g_pw_h[(size_t)CV * CH];    DG float g_pw_l[(size_t)CV * CH];
DG float g_wihs_h[4 * CH * CE];      DG float g_wihs_l[4 * CH * CE];
DG float g_whhs_h[4 * CH * CH];      DG float g_whhs_l[4 * CH * CH];
DG float g_wihr_h[4 * CH * CE];      DG float g_wihr_l[4 * CH * CE];
DG float g_whhr_h[4 * CH * CH];      DG float g_whhr_l[4 * CH * CH];
DG float g_affs_h[CH * CF];          DG float g_affs_l[CH * CF];
DG float g_affr_h[CF * CH];          DG float g_affr_l[CF * CH];
DG float g_tgt_h[(size_t)CB * CF];   DG float g_tgt_l[(size_t)CB * CF];
DG float g_dst_h[(size_t)CD * CB * CF]; DG float g_dst_l[(size_t)CD * CB * CF];
DG float g_r_h[(size_t)CB * CF];     DG float g_r_l[(size_t)CB * CF];
DG float g_hs_h[CB * CH];            DG float g_hs_l[CB * CH];
DG float g_hr_h[CB * CH];            DG float g_hr_l[CB * CH];
DG float g_x_h[CB * CE];             DG float g_x_l[CB * CE];
DG float g_xr_h[CB * CE];            DG float g_xr_l[CB * CE];
DG float g_logits[(size_t)CB * CV];
DG float g_gates[(size_t)CB * 4 * CH];
DG float g_gates_r[(size_t)CB * 4 * CH];
DG float g_hs[CB * CH];
DG float g_hr[CB * CH];
DG float g_cs[CB * CH];
DG float g_cr[CB * CH];
DG float g_lp[CB];
DG float g_r[(size_t)CB * CF];
DG float g_ts[(size_t)CB * CB];
DG float g_ds[(size_t)CD * CB * CB];
DG float g_rowloss[CB];
DG float g_rowcorr[CB];
DG float g_wmax2[1];
DG u32   g_rowmaxk[CB];
DG int   g_msg[CL * CB];

// ---------------- low-level helpers ----------------
__device__ __forceinline__ u32 s2u(const void* p) {
    u32 a; asm("{ .reg .u64 t; cvta.to.shared.u64 t, %1; cvt.u32.u64 %0, t; }" : "=r"(a) : "l"(p));
    return a;
}
__device__ __forceinline__ float tf32r(float x) {
    float r; asm("cvt.rna.tf32.f32 %0, %1;" : "=f"(r) : "f"(x)); return r;
}
__device__ __forceinline__ void cp16(u32 dst, const void* src, bool v) {
    int sz = v ? 16 : 0;
    asm volatile("cp.async.cg.shared.global [%0], [%1], 16, %2;" :: "r"(dst), "l"(src), "r"(sz) : "memory");
}
#define CP_COMMIT() asm volatile("cp.async.commit_group;" ::: "memory")

__device__ __forceinline__ void mma8(float* d, const u32* a, const u32* b) {
    asm volatile(
        "mma.sync.aligned.m16n8k8.row.col.f32.tf32.tf32.f32 "
        "{%0,%1,%2,%3}, {%4,%5,%6,%7}, {%8,%9}, {%0,%1,%2,%3};"
        : "+f"(d[0]), "+f"(d[1]), "+f"(d[2]), "+f"(d[3])
        : "r"(a[0]), "r"(a[1]), "r"(a[2]), "r"(a[3]), "r"(b[0]), "r"(b[1]));
}

// monotonic float<->u32 key (total order, works through atomicMax on u32)
__device__ __forceinline__ u32 fkey(float x) {
    u32 b = __float_as_uint(x);
    return (b & 0x80000000u) ? ~b : (b | 0x80000000u);
}
__device__ __forceinline__ float fdec(u32 k) {
    u32 b = (k & 0x80000000u) ? (k & 0x7fffffffu) : ~k;
    return __uint_as_float(b);
}

// ---------------------------------------------------------------------------
// tf32 NT GEMM (pre-split planes, K-permuted LDS.64 frags). NPASS=3 or 1.
// Optional: rowMaxKey (atomicMax of biased C per row), Ch/Cl (fused tf32 split
// of C written alongside).
// ---------------------------------------------------------------------------
template<int NPASS>
__global__ __launch_bounds__(256, 2)
void tmma_nt(int M, int N,
             const float* __restrict__ A1h, const float* __restrict__ A1l, int K1,
             const float* __restrict__ A2h, const float* __restrict__ A2l, int K2,
             const float* __restrict__ B1h, const float* __restrict__ B1l,
             const float* __restrict__ B2h, const float* __restrict__ B2l,
             const float* __restrict__ bias1, const float* __restrict__ bias2,
             float* __restrict__ C,
             u32* __restrict__ rowMaxKey,
             float* __restrict__ Ch, float* __restrict__ Cl)
{
    extern __shared__ float sm[];
    constexpr int PL = (NPASS == 3) ? 4 : 2;
    constexpr int OAH = 0, OAL = TFL, OBH = (NPASS == 3 ? 2 : 1) * TFL, OBL = 3 * TFL;

    const int tid  = threadIdx.x;
    const int wid  = tid >> 5;
    const int lane = tid & 31;
    const int g    = lane >> 2;
    const int t    = lane & 3;
    const int wm   = (wid & 3) * 32;
    const int wn   = (wid >> 2) * 64;
    const int bn0  = blockIdx.x * BN;
    const int bm0  = blockIdx.y * BM;

    const int nk1 = K1 / BK;
    const int nk2 = A2h ? (K2 / BK) : 0;
    const int nkt = nk1 + nk2;

    auto load_stage = [&](int gkt, int stage) {
        const float *Ah, *Al, *Bh, *Bl; int K, kt;
        if (gkt < nk1) { Ah = A1h; Al = A1l; Bh = B1h; Bl = B1l; K = K1; kt = gkt; }
        else           { Ah = A2h; Al = A2l; Bh = B2h; Bl = B2l; K = K2; kt = gkt - nk1; }
        const int koff = kt * BK;
        float* st = sm + stage * PL * TFL;
        u32 uah = s2u(st + OAH), ubh = s2u(st + OBH);
        u32 ual = s2u(st + OAL), ubl = s2u(st + OBL);
#pragma unroll
        for (int it = 0; it < 2; it++) {
            int c = tid + it * 256;
            int row = c >> 2, ch = c & 3;
            u32 off = (u32)(row * APAD + ch * 4) * 4;
            const size_t ga = (size_t)(bm0 + row) * K + koff + ch * 4;
            cp16(uah + off, Ah + ga, true);
            if (NPASS == 3) cp16(ual + off, Al + ga, true);
            bool v = (bn0 + row) < N;
            const size_t gb = (size_t)(v ? (bn0 + row) : 0) * K + koff + ch * 4;
            cp16(ubh + off, Bh + gb, v);
            if (NPASS == 3) cp16(ubl + off, Bl + gb, v);
        }
        CP_COMMIT();
    };

    float d[2][8][4];
#pragma unroll
    for (int i = 0; i < 2; i++)
#pragma unroll
        for (int j = 0; j < 8; j++)
#pragma unroll
            for (int q = 0; q < 4; q++) d[i][j][q] = 0.f;

    load_stage(0, 0);

    for (int s = 0; s < nkt; s++) {
        if (s + 1 < nkt) {
            load_stage(s + 1, (s + 1) & 1);
            asm volatile("cp.async.wait_group 1;" ::: "memory");
        } else {
            asm volatile("cp.async.wait_group 0;" ::: "memory");
        }
        __syncthreads();

        const float* st  = sm + (s & 1) * PL * TFL;
        const float* pAh = st + OAH;
        const float* pAl = st + OAL;
        const float* pBh = st + OBH;
        const float* pBl = st + OBL;

#pragma unroll
        for (int kk = 0; kk < BK; kk += 8) {
            float2 aH[2][2], aL[2][2];
#pragma unroll
            for (int mt = 0; mt < 2; mt++) {
                const int base = (wm + mt * 16 + g) * APAD + kk + 2 * t;
                aH[mt][0] = *(const float2*)(pAh + base);
                aH[mt][1] = *(const float2*)(pAh + base + 8 * APAD);
                if (NPASS == 3) {
                    aL[mt][0] = *(const float2*)(pAl + base);
                    aL[mt][1] = *(const float2*)(pAl + base + 8 * APAD);
                }
            }
#pragma unroll
            for (int nt = 0; nt < 8; nt++) {
                const int bidx = (wn + nt * 8 + g) * APAD + kk + 2 * t;
                float2 bHf = *(const float2*)(pBh + bidx);
                u32 bH[2] = {__float_as_uint(bHf.x), __float_as_uint(bHf.y)};
                u32 bL[2];
                if (NPASS == 3) {
                    float2 bLf = *(const float2*)(pBl + bidx);
                    bL[0] = __float_as_uint(bLf.x); bL[1] = __float_as_uint(bLf.y);
                }
#pragma unroll
                for (int mt = 0; mt < 2; mt++) {
                    u32 aH4[4] = {__float_as_uint(aH[mt][0].x), __float_as_uint(aH[mt][1].x),
                                  __float_as_uint(aH[mt][0].y), __float_as_uint(aH[mt][1].y)};
                    mma8(d[mt][nt], aH4, bH);
                    if (NPASS == 3) {
                        mma8(d[mt][nt], aH4, bL);
                        u32 aL4[4] = {__float_as_uint(aL[mt][0].x), __float_as_uint(aL[mt][1].x),
                                      __float_as_uint(aL[mt][0].y), __float_as_uint(aL[mt][1].y)};
                        mma8(d[mt][nt], aL4, bH);
                    }
                }
            }
        }
        __syncthreads();
    }

    // epilogue: per-thread rows = {wm+mt*16+g, +8} for mt=0,1
    float rmx[2][2] = {{-3.4e38f, -3.4e38f}, {-3.4e38f, -3.4e38f}};
#pragma unroll
    for (int nt = 0; nt < 8; nt++) {
        const int cb = bn0 + wn + nt * 8;
        if (cb >= N) continue;
        const int col = cb + 2 * t;
        float b0 = 0.f, b1 = 0.f;
        if (bias1) { b0 += bias1[col]; b1 += bias1[col + 1]; }
        if (bias2) { b0 += bias2[col]; b1 += bias2[col + 1]; }
#pragma unroll
        for (int mt = 0; mt < 2; mt++) {
            const int row = bm0 + wm + mt * 16 + g;
            float2 v0 = make_float2(d[mt][nt][0] + b0, d[mt][nt][1] + b1);
            float2 v1 = make_float2(d[mt][nt][2] + b0, d[mt][nt][3] + b1);
            *(float2*)(C + (size_t)row * N + col) = v0;
            *(float2*)(C + (size_t)(row + 8) * N + col) = v1;
            if (rowMaxKey) {
                rmx[mt][0] = fmaxf(rmx[mt][0], fmaxf(v0.x, v0.y));
                rmx[mt][1] = fmaxf(rmx[mt][1], fmaxf(v1.x, v1.y));
            }
            if (Ch) {
                float2 h0, l0, h1, l1;
                h0.x = tf32r(v0.x); l0.x = tf32r(v0.x - h0.x);
                h0.y = tf32r(v0.y); l0.y = tf32r(v0.y - h0.y);
                h1.x = tf32r(v1.x); l1.x = tf32r(v1.x - h1.x);
                h1.y = tf32r(v1.y); l1.y = tf32r(v1.y - h1.y);
                *(float2*)(Ch + (size_t)row * N + col) = h0;
                *(float2*)(Cl + (size_t)row * N + col) = l0;
                *(float2*)(Ch + (size_t)(row + 8) * N + col) = h1;
                *(float2*)(Cl + (size_t)(row + 8) * N + col) = l1;
            }
        }
    }
    if (rowMaxKey) {
#pragma unroll
        for (int mt = 0; mt < 2; mt++) {
            const int row = bm0 + wm + mt * 16 + g;
            atomicMax(&rowMaxKey[row],     fkey(rmx[mt][0]));
            atomicMax(&rowMaxKey[row + 8], fkey(rmx[mt][1]));
        }
    }
}

// ---------------- fused prepass ----------------
struct PJ { const float4* s; float4* h; float4* l; };
struct PrepArgs {
    PJ j[9];
    float4* z[4];           // cs, cr, hrh, hrl
    float* wmax2;
};
constexpr size_t N4_PW   = (size_t)CV * CH / 4;
constexpr size_t N4_WIH  = (size_t)CH * CE;
constexpr size_t N4_WHH  = (size_t)CH * CH;
constexpr size_t N4_AFF  = (size_t)CH * CF / 4;
constexpr size_t N4_TGT  = (size_t)CB * CF / 4;
constexpr size_t N4_DST  = (size_t)CD * CB * CF / 4;
constexpr size_t N4_Z    = (size_t)CB * CH / 4;
constexpr size_t SPLIT_TOT = N4_PW + 2 * N4_WIH + 2 * N4_WHH + 2 * N4_AFF + N4_TGT + N4_DST;
constexpr size_t PREP_TOT = SPLIT_TOT + 4 * N4_Z;

__global__ void prep_all(PrepArgs a)
{
    constexpr size_t JS[9] = {N4_PW, N4_WIH, N4_WHH, N4_WIH, N4_WHH, N4_AFF, N4_AFF, N4_TGT, N4_DST};

    if (blockIdx.x == 0 && threadIdx.x == 0) a.wmax2[0] = 0.f;
    const size_t stride = (size_t)gridDim.x * blockDim.x;
    for (size_t i = (size_t)blockIdx.x * blockDim.x + threadIdx.x; i < PREP_TOT; i += stride) {
        if (i >= SPLIT_TOT) {
            size_t r = i - SPLIT_TOT;
            a.z[r / N4_Z][r % N4_Z] = make_float4(0.f, 0.f, 0.f, 0.f);
            continue;
        }
        size_t r = i;
        int job = 0;
#pragma unroll
        for (int q = 0; q < 8; q++) {
            if (r >= JS[q] && job == q) { r -= JS[q]; job = q + 1; }
        }
        float4 s = a.j[job].s[r];
        float4 h, l;
        h.x = tf32r(s.x); l.x = tf32r(s.x - h.x);
        h.y = tf32r(s.y); l.y = tf32r(s.y - h.y);
        h.z = tf32r(s.z); l.z = tf32r(s.z - h.z);
        h.w = tf32r(s.w); l.w = tf32r(s.w - h.w);
        a.j[job].h[r] = h; a.j[job].l[r] = l;
    }
}

// ---------------- elementwise kernels ----------------
__global__ void gather_split_k(const int* __restrict__ tok, const int* __restrict__ sidx,
                               const float* __restrict__ emb,
                               float* __restrict__ xh, float* __restrict__ xl,
                               u32* __restrict__ rstmax)
{
    int i = blockIdx.x * blockDim.x + threadIdx.x;
    if (i >= CB * (CE / 4)) return;
    if (rstmax && i < CB) rstmax[i] = 0u;   // smallest key
    int b = i / (CE / 4), j = (i % (CE / 4)) * 4;
    int tk = tok ? tok[b] : sidx[0];
    float4 e = *(const float4*)(emb + (size_t)tk * CE + j);
    float4 h, l;
    h.x = tf32r(e.x); l.x = tf32r(e.x - h.x);
    h.y = tf32r(e.y); l.y = tf32r(e.y - h.y);
    h.z = tf32r(e.z); l.z = tf32r(e.z - h.z);
    h.w = tf32r(e.w); l.w = tf32r(e.w - h.w);
    *(float4*)(xh + (size_t)b * CE + j) = h;
    *(float4*)(xl + (size_t)b * CE + j) = l;
}

__global__ void lstm_cell_split(const float* __restrict__ gates, float* __restrict__ c,
                                float* __restrict__ hraw,
                                float* __restrict__ hhi, float* __restrict__ hlo)
{
    const int t = blockIdx.x * blockDim.x + threadIdx.x;
    if (t >= CB * CH) return;
    const int b = t >> 10, j = t & 1023;
    const float* g = gates + (size_t)b * (4 * CH);
    const float gi = g[j], gf = g[CH + j], gg = g[2 * CH + j], go = g[3 * CH + j];
    const float ig = 1.f / (1.f + __expf(-gi));
    const float fg = 1.f / (1.f + __expf(-gf));
    const float og = 1.f / (1.f + __expf(-go));
    const float cn = fg * c[t] + ig * tanhf(gg);
    c[t] = cn;
    const float h = og * tanhf(cn);
    hraw[t] = h;
    const float hh = tf32r(h);
    hhi[t] = hh;
    hlo[t] = tf32r(h - hh);
}

// max squared row-norm of probs_W
__global__ void wnorms_max(const float* __restrict__ W, float* __restrict__ wmax2)
{
    const int row = blockIdx.x * 8 + (threadIdx.x >> 5);
    const int lane = threadIdx.x & 31;
    if (row >= CV) return;
    const float* w = W + (size_t)row * CH;
    float s = 0.f;
    for (int k = lane; k < CH; k += 32) { float v = w[k]; s += v * v; }
#pragma unroll
    for (int st = 16; st > 0; st >>= 1) s += __shfl_xor_sync(0xffffffff, s, st);
    if (lane == 0) atomicMax((int*)wmax2, __float_as_int(s));
}

// argmax over tf32 phase-1 logits + exact fp32 rescue.
// If rowMaxKey != null (and !want_lp): skip the max scan, use decoded max.
__global__ void logits_argmax(const float* __restrict__ logits,
                              const float* __restrict__ h,
                              const float* __restrict__ W,
                              const float* __restrict__ pb,
                              const float* __restrict__ wmax2,
                              const u32* __restrict__ rowMaxKey,
                              int* __restrict__ tok, float* __restrict__ lp,
                              int want_lp, int mshift)
{
    const int b = blockIdx.x;
    const int tid = threadIdx.x;
    __shared__ float sh[CH];
    __shared__ float smx[256], ssm[256];
    __shared__ int   sidx[256];

    float nrm = 0.f;
    for (int i = tid; i < CH; i += 256) { float v = h[(size_t)b * CH + i]; sh[i] = v; nrm += v * v; }
    smx[tid] = nrm;
    __syncthreads();
    for (int st = 128; st > 0; st >>= 1) {
        if (tid < st) smx[tid] += smx[tid + st];
        __syncthreads();
    }
    const float hn2 = smx[0];
    __syncthreads();

    float mall, sall = 0.f;
    if (!want_lp && rowMaxKey) {
        mall = fdec(rowMaxKey[b]);
    } else {
        const float4* row4 = (const float4*)(logits + (size_t)b * CV);
        float m = -3.4e38f, s = 0.f;
        for (int j4 = tid; j4 < CV / 4; j4 += 256) {
            float4 v = row4[j4];
            float xs[4] = {v.x, v.y, v.z, v.w};
#pragma unroll
            for (int c = 0; c < 4; c++) {
                float x = xs[c];
                if (x > m) {
                    if (want_lp) s = s * expf(m - x) + 1.f;
                    m = x;
                } else if (want_lp) {
                    s += expf(x - m);
                }
            }
        }
        smx[tid] = m; ssm[tid] = s;
        __syncthreads();
        for (int st = 128; st > 0; st >>= 1) {
            if (tid < st) {
                float m1 = smx[tid], s1 = ssm[tid];
                float m2 = smx[tid + st], s2 = ssm[tid + st];
                if (m2 > m1) { smx[tid] = m2; ssm[tid] = s2 + s1 * expf(m1 - m2); }
                else         { ssm[tid] = s1 + s2 * expf(m2 - m1); }
            }
            __syncthreads();
        }
        mall = smx[0];
        sall = ssm[0];
        __syncthreads();
    }

    const float margin = ldexpf(sqrtf(hn2 * wmax2[0]), mshift);
    const float thr = mall - margin;

    const float* row = logits + (size_t)b * CV;
    float bv = -3.4e38f; int bi = 0x7fffffff;
    for (int j = tid; j < CV; j += 256) {
        if (row[j] >= thr) {
            const float* w = W + (size_t)j * CH;
            float dot = pb[j];
#pragma unroll 4
            for (int k = 0; k < CH; k++) dot = fmaf(sh[k], w[k], dot);
            if (dot > bv || (dot == bv && j < bi)) { bv = dot; bi = j; }
        }
    }
    smx[tid] = bv; sidx[tid] = bi;
    __syncthreads();
    for (int st = 128; st > 0; st >>= 1) {
        if (tid < st) {
            float v2 = smx[tid + st]; int i2 = sidx[tid + st];
            if (v2 > smx[tid] || (v2 == smx[tid] && i2 < sidx[tid])) { smx[tid] = v2; sidx[tid] = i2; }
        }
        __syncthreads();
    }
    if (tid == 0) {
        tok[b] = sidx[0];
        if (want_lp) lp[b] = smx[0] - (mall + logf(sall));
    }
}

// ---------------- hinge loss / accuracy reductions ----------------
__global__ void score_rows(const float* __restrict__ ts, const float* __restrict__ ds,
                           const float* __restrict__ lp,
                           float* __restrict__ rowloss, float* __restrict__ rowcorr)
{
    const int i = blockIdx.x;
    const float* trow = ts + (size_t)i * CB;
    const float* dr0 = ds + 0ULL * CB * CB + (size_t)i * CB;
    const float* dr1 = ds + 1ULL * CB * CB + (size_t)i * CB;
    const float* dr2 = ds + 2ULL * CB * CB + (size_t)i * CB;
    const float* dr3 = ds + 3ULL * CB * CB + (size_t)i * CB;

    float ls = 0.f, et = 0.f, e0 = 0.f, e1 = 0.f, e2 = 0.f, e3 = 0.f;
    for (int j = threadIdx.x; j < CB; j += 256) {
        const float t  = trow[j];
        const float a0 = dr0[j], a1 = dr1[j], a2 = dr2[j], a3 = dr3[j];
        float h = fmaxf(0.f, 1.f - t + a0) + fmaxf(0.f, 1.f - t + a1)
                + fmaxf(0.f, 1.f - t + a2) + fmaxf(0.f, 1.f - t + a3);
        ls += h * lp[j];
        et += expf(t); e0 += expf(a0); e1 += expf(a1); e2 += expf(a2); e3 += expf(a3);
    }
    __shared__ float red[6][256];
    red[0][threadIdx.x] = ls; red[1][threadIdx.x] = et;
    red[2][threadIdx.x] = e0; red[3][threadIdx.x] = e1;
    red[4][threadIdx.x] = e2; red[5][threadIdx.x] = e3;
    __syncthreads();
    for (int st = 128; st > 0; st >>= 1) {
        if (threadIdx.x < st)
#pragma unroll
            for (int q = 0; q < 6; q++) red[q][threadIdx.x] += red[q][threadIdx.x + st];
        __syncthreads();
    }
    if (threadIdx.x == 0) {
        rowloss[i] = red[0][0];
        const float tp = red[1][0] / (float)CB;
        const float mx = fmaxf(fmaxf(red[2][0], red[3][0]), fmaxf(red[4][0], red[5][0])) / (float)CB;
        rowcorr[i] = (tp >= mx) ? 1.f : 0.f;
    }
}

__global__ void final_reduce(const float* __restrict__ rowloss,
                             const float* __restrict__ rowcorr, float* __restrict__ out)
{
    __shared__ float s1[256], s2[256];
    float a = 0.f, b = 0.f;
    for (int i = threadIdx.x; i < CB; i += 256) { a += rowloss[i]; b += rowcorr[i]; }
    s1[threadIdx.x] = a; s2[threadIdx.x] = b;
    __syncthreads();
    for (int st = 128; st > 0; st >>= 1) {
        if (threadIdx.x < st) { s1[threadIdx.x] += s1[threadIdx.x + st]; s2[threadIdx.x] += s2[threadIdx.x + st]; }
        __syncthreads();
    }
    if (threadIdx.x == 0) {
        out[0] = -s1[0] / (float)((size_t)CB * CB);
        out[1] =  s2[0] / (float)CB;
    }
}

// ---------------------------------------------------------------------------
extern "C" void kernel_launch(void* const* d_in, const int* in_sizes, int n_in,
                              void* d_out, int out_size)
{
    (void)in_sizes; (void)n_in; (void)out_size;
    const float* target   = (const float*)d_in[0];
    const float* distract = (const float*)d_in[1];
    const int*   sidx     = (const int*)d_in[2];
    const float* emb_s   = (const float*)d_in[4];
    const float* Wih_s   = (const float*)d_in[5];
    const float* Whh_s   = (const float*)d_in[6];
    const float* bih_s   = (const float*)d_in[7];
    const float* bhh_s   = (const float*)d_in[8];
    const float* aff_s_W = (const float*)d_in[9];
    const float* aff_s_b = (const float*)d_in[10];
    const float* probs_W = (const float*)d_in[11];
    const float* probs_b = (const float*)d_in[12];
    const float* emb_r   = (const float*)d_in[13];
    const float* Wih_r   = (const float*)d_in[14];
    const float* Whh_r   = (const float*)d_in[15];
    const float* bih_r   = (const float*)d_in[16];
    const float* bhh_r   = (const float*)d_in[17];
    const float* aff_r_W = (const float*)d_in[18];
    const float* aff_r_b = (const float*)d_in[19];
    float* out = (float*)d_out;

    static cudaStream_t s2 = nullptr;
    static cudaEvent_t evFork = nullptr, evJoin = nullptr, evTok[CL];
    if (!s2) {
        cudaStreamCreateWithFlags(&s2, cudaStreamNonBlocking);
        cudaEventCreateWithFlags(&evFork, cudaEventDisableTiming);
        cudaEventCreateWithFlags(&evJoin, cudaEventDisableTiming);
        for (int t = 0; t < CL; t++) cudaEventCreateWithFlags(&evTok[t], cudaEventDisableTiming);
    }

    cudaFuncSetAttribute(tmma_nt<3>, cudaFuncAttributeMaxDynamicSharedMemorySize, SMEM3);
    cudaFuncSetAttribute(tmma_nt<1>, cudaFuncAttributeMaxDynamicSharedMemorySize, SMEM1);

#define SYM(T, p, s) T* p; cudaGetSymbolAddress((void**)&p, s)
    SYM(float, pwh, g_pw_h); SYM(float, pwl, g_pw_l);
    SYM(float, wihsh, g_wihs_h); SYM(float, wihsl, g_wihs_l);
    SYM(float, whhsh, g_whhs_h); SYM(float, whhsl, g_whhs_l);
    SYM(float, wihrh, g_wihr_h); SYM(float, wihrl, g_wihr_l);
    SYM(float, whhrh, g_whhr_h); SYM(float, whhrl, g_whhr_l);
    SYM(float, affsh, g_affs_h); SYM(float, affsl, g_affs_l);
    SYM(float, affrh, g_affr_h); SYM(float, affrl, g_affr_l);
    SYM(float, tgth, g_tgt_h);   SYM(float, tgtl, g_tgt_l);
    SYM(float, dsth, g_dst_h);   SYM(float, dstl, g_dst_l);
    SYM(float, rh, g_r_h);       SYM(float, rl, g_r_l);
    SYM(float, hsh, g_hs_h);     SYM(float, hsl, g_hs_l);
    SYM(float, hrh, g_hr_h);     SYM(float, hrl, g_hr_l);
    SYM(float, xh, g_x_h);       SYM(float, xl, g_x_l);
    SYM(float, xrh, g_xr_h);     SYM(float, xrl, g_xr_l);
    SYM(float, p_logits, g_logits); SYM(float, p_gates, g_gates); SYM(float, p_gates_r, g_gates_r);
    SYM(float, p_hs, g_hs); SYM(float, p_hr, g_hr); SYM(float, p_cs, g_cs); SYM(float, p_cr, g_cr);
    SYM(float, p_lp, g_lp); SYM(float, p_r, g_r); SYM(float, p_ts, g_ts); SYM(float, p_ds, g_ds);
    SYM(float, p_rowloss, g_rowloss); SYM(float, p_rowcorr, g_rowcorr);
    SYM(float, p_wmax2, g_wmax2);
    SYM(u32, p_rmk, g_rowmaxk);
    SYM(int, p_msg, g_msg);
#undef SYM

    // ---- fused prepass (splits + zeros + wmax2 init) ----
    PrepArgs pa;
    pa.j[0] = {(const float4*)probs_W,  (float4*)pwh,   (float4*)pwl};
    pa.j[1] = {(const float4*)Wih_s,    (float4*)wihsh, (float4*)wihsl};
    pa.j[2] = {(const float4*)Whh_s,    (float4*)whhsh, (float4*)whhsl};
    pa.j[3] = {(const float4*)Wih_r,    (float4*)wihrh, (float4*)wihrl};
    pa.j[4] = {(const float4*)Whh_r,    (float4*)whhrh, (float4*)whhrl};
    pa.j[5] = {(const float4*)aff_s_W,  (float4*)affsh, (float4*)affsl};
    pa.j[6] = {(const float4*)aff_r_W,  (float4*)affrh, (float4*)affrl};
    pa.j[7] = {(const float4*)target,   (float4*)tgth,  (float4*)tgtl};
    pa.j[8] = {(const float4*)distract, (float4*)dsth,  (float4*)dstl};
    pa.z[0] = (float4*)p_cs; pa.z[1] = (float4*)p_cr;
    pa.z[2] = (float4*)hrh;  pa.z[3] = (float4*)hrl;
    pa.wmax2 = p_wmax2;
    prep_all<<<2048, 256>>>(pa);

    wnorms_max<<<(CV + 7) / 8, 256>>>(probs_W, p_wmax2);

    cudaEventRecord(evFork, 0);
    cudaStreamWaitEvent(s2, evFork, 0);

    // h0 = target @ aff_s_W^T + aff_s_b  (split fused into epilogue)
    tmma_nt<3><<<dim3(CH / BN, CB / BM), 256, SMEM3>>>(CB, CH,
        tgth, tgtl, CF, nullptr, nullptr, 0,
        affsh, affsl, nullptr, nullptr, aff_s_b, nullptr, p_hs,
        nullptr, hsh, hsl);

    // ---- sender (stream 0) ----
    for (int t = 0; t < CL; t++) {
        const int* tokidx = (t == 0) ? nullptr : (p_msg + (t - 1) * CB);
        gather_split_k<<<(CB * CE / 4 + 255) / 256, 256>>>(tokidx, sidx, emb_s, xh, xl, p_rmk);
        tmma_nt<3><<<dim3(4 * CH / BN, CB / BM), 256, SMEM3>>>(CB, 4 * CH,
            xh, xl, CE, hsh, hsl, CH,
            wihsh, wihsl, whhsh, whhsl, bih_s, bhh_s, p_gates,
            nullptr, nullptr, nullptr);
        lstm_cell_split<<<(CB * CH) / 256, 256>>>(p_gates, p_cs, p_hs, hsh, hsl);
        const int last = (t == CL - 1);
        tmma_nt<1><<<dim3((CV + BN - 1) / BN, CB / BM), 256, SMEM1>>>(CB, CV,
            hsh, nullptr, CH, nullptr, nullptr, 0,
            pwh, nullptr, nullptr, nullptr, probs_b, nullptr, p_logits,
            last ? nullptr : p_rmk, nullptr, nullptr);
        logits_argmax<<<CB, 256>>>(p_logits, p_hs, probs_W, probs_b, p_wmax2,
                                   last ? nullptr : p_rmk,
                                   p_msg + t * CB, p_lp, last, -8);
        cudaEventRecord(evTok[t], 0);
    }

    // ---- receiver (stream s2, overlapped) ----
    for (int t = 0; t < CL; t++) {
        cudaStreamWaitEvent(s2, evTok[t], 0);
        gather_split_k<<<(CB * CE / 4 + 255) / 256, 256, 0, s2>>>(p_msg + t * CB, sidx, emb_r, xrh, xrl, nullptr);
        tmma_nt<3><<<dim3(4 * CH / BN, CB / BM), 256, SMEM3, s2>>>(CB, 4 * CH,
            xrh, xrl, CE, hrh, hrl, CH,
            wihrh, wihrl, whhrh, whhrl, bih_r, bhh_r, p_gates_r,
            nullptr, nullptr, nullptr);
        lstm_cell_split<<<(CB * CH) / 256, 256, 0, s2>>>(p_gates_r, p_cr, p_hr, hrh, hrl);
    }
    cudaEventRecord(evJoin, s2);
    cudaStreamWaitEvent(0, evJoin, 0);

    // r = hr @ aff_r_W^T + aff_r_b  (split fused into epilogue)
    tmma_nt<3><<<dim3(CF / BN, CB / BM), 256, SMEM3>>>(CB, CF,
        hrh, hrl, CH, nullptr, nullptr, 0,
        affrh, affrl, nullptr, nullptr, aff_r_b, nullptr, p_r,
        nullptr, rh, rl);

    // ts = target @ r^T ; ds = distractors @ r^T
    tmma_nt<3><<<dim3(CB / BN, CB / BM), 256, SMEM3>>>(CB, CB,
        tgth, tgtl, CF, nullptr, nullptr, 0,
        rh, rl, nullptr, nullptr, nullptr, nullptr, p_ts,
        nullptr, nullptr, nullptr);
    tmma_nt<3><<<dim3(CB / BN, (CD * CB) / BM), 256, SMEM3>>>(CD * CB, CB,
        dsth, dstl, CF, nullptr, nullptr, 0,
        rh, rl, nullptr, nullptr, nullptr, nullptr, p_ds,
        nullptr, nullptr, nullptr);

    score_rows<<<CB, 256>>>(p_ts, p_ds, p_lp, p_rowloss, p_rowcorr);
    final_reduce<<<1, 256>>>(p_rowloss, p_rowcorr, out);
}

// round 15
// speedup vs baseline: 1.0486x; 1.0126x over previous
#include <cuda_runtime.h>
#include <cuda_bf16.h>
#include <cstdint>

typedef unsigned long long u64;
typedef uint32_t u32;

constexpr int CB = 1024;   // batch
constexpr int CF = 4096;   // feature
constexpr int CV = 20000;  // vocab
constexpr int CE = 512;    // embed dim
constexpr int CH = 1024;   // hidden
constexpr int CL = 20;     // sentence length
constexpr int CD = 4;      // distractors

// ---------------- tf32 GEMM tiling ----------------
constexpr int BM = 128, BN = 128, BK = 16;
constexpr int APAD = 24;                 // float row pitch: conflict-free LDS.64 frags
constexpr int TFL = BM * APAD;
// NPASS=3 uses 2 stages x 4 planes; NPASS=1 uses 4 stages x 2 planes: both 8*TFL floats
constexpr int SMEM_G = 8 * TFL * 4 + 512;   // + 512B for gather index cache

// ---------------- scratch (static device globals; no allocation) ----------------
#define DG __device__ __align__(256)
DG float g_pw_h[(size_t)CV * CH];    DG float g_pw_l[(size_t)CV * CH];
DG float g_embs_h[(size_t)CV * CE];  DG float g_embs_l[(size_t)CV * CE];
DG float g_embr_h[(size_t)CV * CE];  DG float g_embr_l[(size_t)CV * CE];
DG float g_wihs_h[4 * CH * CE];      DG float g_wihs_l[4 * CH * CE];
DG float g_whhs_h[4 * CH * CH];      DG float g_whhs_l[4 * CH * CH];
DG float g_wihr_h[4 * CH * CE];      DG float g_wihr_l[4 * CH * CE];
DG float g_whhr_h[4 * CH * CH];      DG float g_whhr_l[4 * CH * CH];
DG float g_affs_h[CH * CF];          DG float g_affs_l[CH * CF];
DG float g_affr_h[CF * CH];          DG float g_affr_l[CF * CH];
DG float g_tgt_h[(size_t)CB * CF];   DG float g_tgt_l[(size_t)CB * CF];
DG float g_dst_h[(size_t)CD * CB * CF]; DG float g_dst_l[(size_t)CD * CB * CF];
DG float g_r_h[(size_t)CB * CF];     DG float g_r_l[(size_t)CB * CF];
DG float g_hs_h[CB * CH];            DG float g_hs_l[CB * CH];
DG float g_hr_h[CB * CH];            DG float g_hr_l[CB * CH];
DG float g_logits[(size_t)CB * CV];                // fp32 (t=19 only)
DG __nv_bfloat16 g_logits_bf[(size_t)CB * CV];     // bf16 (t<19)
DG float g_gates[(size_t)CB * 4 * CH];
DG float g_gates_r[(size_t)CB * 4 * CH];
DG float g_hs[CB * CH];
DG float g_hr[CB * CH];
DG float g_cs[CB * CH];
DG float g_cr[CB * CH];
DG float g_lp[CB];
DG float g_r[(size_t)CB * CF];
DG float g_ts[(size_t)CB * CB];
DG float g_ds[(size_t)CD * CB * CB];
DG float g_rowloss[CB];
DG float g_rowcorr[CB];
DG float g_wmax2[1];
DG u32   g_rowmaxk[CB];
DG int   g_msg[CL * CB];

// ---------------- low-level helpers ----------------
__device__ __forceinline__ u32 s2u(const void* p) {
    u32 a; asm("{ .reg .u64 t; cvta.to.shared.u64 t, %1; cvt.u32.u64 %0, t; }" : "=r"(a) : "l"(p));
    return a;
}
__device__ __forceinline__ float tf32r(float x) {
    float r; asm("cvt.rna.tf32.f32 %0, %1;" : "=f"(r) : "f"(x)); return r;
}
__device__ __forceinline__ void cp16(u32 dst, const void* src, bool v) {
    int sz = v ? 16 : 0;
    asm volatile("cp.async.cg.shared.global [%0], [%1], 16, %2;" :: "r"(dst), "l"(src), "r"(sz) : "memory");
}
#define CP_COMMIT() asm volatile("cp.async.commit_group;" ::: "memory")

__device__ __forceinline__ void mma8(float* d, const u32* a, const u32* b) {
    asm volatile(
        "mma.sync.aligned.m16n8k8.row.col.f32.tf32.tf32.f32 "
        "{%0,%1,%2,%3}, {%4,%5,%6,%7}, {%8,%9}, {%0,%1,%2,%3};"
        : "+f"(d[0]), "+f"(d[1]), "+f"(d[2]), "+f"(d[3])
        : "r"(a[0]), "r"(a[1]), "r"(a[2]), "r"(a[3]), "r"(b[0]), "r"(b[1]));
}

// monotonic float<->u32 key (total order through atomicMax on u32)
__device__ __forceinline__ u32 fkey(float x) {
    u32 b = __float_as_uint(x);
    return (b & 0x80000000u) ? ~b : (b | 0x80000000u);
}
__device__ __forceinline__ float fdec(u32 k) {
    u32 b = (k & 0x80000000u) ? (k & 0x7fffffffu) : ~k;
    return __uint_as_float(b);
}

// ---------------------------------------------------------------------------
// tf32 NT GEMM (pre-split planes, K-permuted LDS.64 frags).
// NPASS=3 (full split, 2 stages) or NPASS=1 (hi only, 4 stages).
// Pass-1 A rows optionally gathered: row -> gidx[row] (or stok[0] if gidx null).
// Outputs: C (fp32, optional), Cbf (bf16, optional), Ch/Cl (fused tf32 split),
// rowMaxKey (atomicMax of biased values per row).
// ---------------------------------------------------------------------------
template<int NPASS, int NSTAGE>
__global__ __launch_bounds__(256, 2)
void tmma_nt(int M, int N,
             const float* __restrict__ A1h, const float* __restrict__ A1l, int K1,
             const int* __restrict__ gidx, const int* __restrict__ stok,
             const float* __restrict__ A2h, const float* __restrict__ A2l, int K2,
             const float* __restrict__ B1h, const float* __restrict__ B1l,
             const float* __restrict__ B2h, const float* __restrict__ B2l,
             const float* __restrict__ bias1, const float* __restrict__ bias2,
             float* __restrict__ C, __nv_bfloat16* __restrict__ Cbf,
             u32* __restrict__ rowMaxKey,
             float* __restrict__ Ch, float* __restrict__ Cl)
{
    extern __shared__ float sm[];
    constexpr int PL = (NPASS == 3) ? 4 : 2;
    constexpr int OAH = 0, OAL = TFL, OBH = (NPASS == 3 ? 2 : 1) * TFL, OBL = 3 * TFL;
    int* sIdx = (int*)(sm + NSTAGE * PL * TFL);

    const int tid  = threadIdx.x;
    const int wid  = tid >> 5;
    const int lane = tid & 31;
    const int g    = lane >> 2;
    const int t    = lane & 3;
    const int wm   = (wid & 3) * 32;
    const int wn   = (wid >> 2) * 64;
    const int bn0  = blockIdx.x * BN;
    const int bm0  = blockIdx.y * BM;

    const bool useIdx = (gidx != nullptr) || (stok != nullptr);
    if (useIdx && tid < BM) sIdx[tid] = gidx ? gidx[bm0 + tid] : stok[0];
    if (useIdx) __syncthreads();

    const int nk1 = K1 / BK;
    const int nk2 = A2h ? (K2 / BK) : 0;
    const int nkt = nk1 + nk2;

    auto load_stage = [&](int gkt, int slot) {
        const float *Ah, *Al, *Bh, *Bl; int K, kt; bool gath;
        if (gkt < nk1) { Ah = A1h; Al = A1l; Bh = B1h; Bl = B1l; K = K1; kt = gkt; gath = useIdx; }
        else           { Ah = A2h; Al = A2l; Bh = B2h; Bl = B2l; K = K2; kt = gkt - nk1; gath = false; }
        const int koff = kt * BK;
        float* st = sm + slot * PL * TFL;
        u32 uah = s2u(st + OAH), ubh = s2u(st + OBH);
        u32 ual = s2u(st + OAL), ubl = s2u(st + OBL);
#pragma unroll
        for (int it = 0; it < 2; it++) {
            int c = tid + it * 256;
            int row = c >> 2, ch = c & 3;
            u32 off = (u32)(row * APAD + ch * 4) * 4;
            const size_t arow = gath ? (size_t)sIdx[row] : (size_t)(bm0 + row);
            const size_t ga = arow * K + koff + ch * 4;
            cp16(uah + off, Ah + ga, true);
            if (NPASS == 3) cp16(ual + off, Al + ga, true);
            bool v = (bn0 + row) < N;
            const size_t gb = (size_t)(v ? (bn0 + row) : 0) * K + koff + ch * 4;
            cp16(ubh + off, Bh + gb, v);
            if (NPASS == 3) cp16(ubl + off, Bl + gb, v);
        }
        CP_COMMIT();
    };

    float d[2][8][4];
#pragma unroll
    for (int i = 0; i < 2; i++)
#pragma unroll
        for (int j = 0; j < 8; j++)
#pragma unroll
            for (int q = 0; q < 4; q++) d[i][j][q] = 0.f;

    int loaded = (nkt < NSTAGE - 1) ? nkt : (NSTAGE - 1);
    for (int p = 0; p < loaded; p++) load_stage(p, p % NSTAGE);

    for (int s = 0; s < nkt; s++) {
        if (loaded < nkt) {
            asm volatile("cp.async.wait_group %0;" :: "n"(NSTAGE - 2) : "memory");
        } else {
            asm volatile("cp.async.wait_group 0;" ::: "memory");
        }
        __syncthreads();
        if (loaded < nkt) { load_stage(loaded, loaded % NSTAGE); loaded++; }

        const float* st  = sm + (s % NSTAGE) * PL * TFL;
        const float* pAh = st + OAH;
        const float* pAl = st + OAL;
        const float* pBh = st + OBH;
        const float* pBl = st + OBL;

#pragma unroll
        for (int kk = 0; kk < BK; kk += 8) {
            float2 aH[2][2], aL[2][2];
#pragma unroll
            for (int mt = 0; mt < 2; mt++) {
                const int base = (wm + mt * 16 + g) * APAD + kk + 2 * t;
                aH[mt][0] = *(const float2*)(pAh + base);
                aH[mt][1] = *(const float2*)(pAh + base + 8 * APAD);
                if (NPASS == 3) {
                    aL[mt][0] = *(const float2*)(pAl + base);
                    aL[mt][1] = *(const float2*)(pAl + base + 8 * APAD);
                }
            }
#pragma unroll
            for (int nt = 0; nt < 8; nt++) {
                const int bidx = (wn + nt * 8 + g) * APAD + kk + 2 * t;
                float2 bHf = *(const float2*)(pBh + bidx);
                u32 bH[2] = {__float_as_uint(bHf.x), __float_as_uint(bHf.y)};
                u32 bL[2];
                if (NPASS == 3) {
                    float2 bLf = *(const float2*)(pBl + bidx);
                    bL[0] = __float_as_uint(bLf.x); bL[1] = __float_as_uint(bLf.y);
                }
#pragma unroll
                for (int mt = 0; mt < 2; mt++) {
                    u32 aH4[4] = {__float_as_uint(aH[mt][0].x), __float_as_uint(aH[mt][1].x),
                                  __float_as_uint(aH[mt][0].y), __float_as_uint(aH[mt][1].y)};
                    mma8(d[mt][nt], aH4, bH);
                    if (NPASS == 3) {
                        mma8(d[mt][nt], aH4, bL);
                        u32 aL4[4] = {__float_as_uint(aL[mt][0].x), __float_as_uint(aL[mt][1].x),
                                      __float_as_uint(aL[mt][0].y), __float_as_uint(aL[mt][1].y)};
                        mma8(d[mt][nt], aL4, bH);
                    }
                }
            }
        }
        __syncthreads();
    }

    // epilogue: per-thread rows = {wm+mt*16+g, +8}
    float rmx[2][2] = {{-3.4e38f, -3.4e38f}, {-3.4e38f, -3.4e38f}};
#pragma unroll
    for (int nt = 0; nt < 8; nt++) {
        const int cb = bn0 + wn + nt * 8;
        if (cb >= N) continue;
        const int col = cb + 2 * t;
        float b0 = 0.f, b1 = 0.f;
        if (bias1) { b0 += bias1[col]; b1 += bias1[col + 1]; }
        if (bias2) { b0 += bias2[col]; b1 += bias2[col + 1]; }
#pragma unroll
        for (int mt = 0; mt < 2; mt++) {
            const int row = bm0 + wm + mt * 16 + g;
            float2 v0 = make_float2(d[mt][nt][0] + b0, d[mt][nt][1] + b1);
            float2 v1 = make_float2(d[mt][nt][2] + b0, d[mt][nt][3] + b1);
            if (C) {
                *(float2*)(C + (size_t)row * N + col) = v0;
                *(float2*)(C + (size_t)(row + 8) * N + col) = v1;
            }
            if (Cbf) {
                *(__nv_bfloat162*)(Cbf + (size_t)row * N + col) = __floats2bfloat162_rn(v0.x, v0.y);
                *(__nv_bfloat162*)(Cbf + (size_t)(row + 8) * N + col) = __floats2bfloat162_rn(v1.x, v1.y);
            }
            if (rowMaxKey) {
                rmx[mt][0] = fmaxf(rmx[mt][0], fmaxf(v0.x, v0.y));
                rmx[mt][1] = fmaxf(rmx[mt][1], fmaxf(v1.x, v1.y));
            }
            if (Ch) {
                float2 h0, l0, h1, l1;
                h0.x = tf32r(v0.x); l0.x = tf32r(v0.x - h0.x);
                h0.y = tf32r(v0.y); l0.y = tf32r(v0.y - h0.y);
                h1.x = tf32r(v1.x); l1.x = tf32r(v1.x - h1.x);
                h1.y = tf32r(v1.y); l1.y = tf32r(v1.y - h1.y);
                *(float2*)(Ch + (size_t)row * N + col) = h0;
                *(float2*)(Cl + (size_t)row * N + col) = l0;
                *(float2*)(Ch + (size_t)(row + 8) * N + col) = h1;
                *(float2*)(Cl + (size_t)(row + 8) * N + col) = l1;
            }
        }
    }
    if (rowMaxKey) {
#pragma unroll
        for (int mt = 0; mt < 2; mt++) {
            const int row = bm0 + wm + mt * 16 + g;
            atomicMax(&rowMaxKey[row],     fkey(rmx[mt][0]));
            atomicMax(&rowMaxKey[row + 8], fkey(rmx[mt][1]));
        }
    }
}

// ---------------- generic prepass (split planes + zero fills) ----------------
struct PJ { const float4* s; float4* h; float4* l; };
struct PrepArgs {
    PJ j[6]; size_t jsz[6]; int nj;
    float4* z[3]; int nz; size_t zsz;
    float* wmax2; int initw;
    size_t split_tot, tot;
};

__global__ void prep_all(PrepArgs a)
{
    if (a.initw && blockIdx.x == 0 && threadIdx.x == 0) a.wmax2[0] = 0.f;
    const size_t stride = (size_t)gridDim.x * blockDim.x;
    for (size_t i = (size_t)blockIdx.x * blockDim.x + threadIdx.x; i < a.tot; i += stride) {
        if (i >= a.split_tot) {
            size_t r = i - a.split_tot;
            a.z[r / a.zsz][r % a.zsz] = make_float4(0.f, 0.f, 0.f, 0.f);
            continue;
        }
        size_t r = i;
        int job = 0;
        while (job < a.nj - 1 && r >= a.jsz[job]) { r -= a.jsz[job]; job++; }
        float4 s = a.j[job].s[r];
        float4 h, l;
        h.x = tf32r(s.x); l.x = tf32r(s.x - h.x);
        h.y = tf32r(s.y); l.y = tf32r(s.y - h.y);
        h.z = tf32r(s.z); l.z = tf32r(s.z - h.z);
        h.w = tf32r(s.w); l.w = tf32r(s.w - h.w);
        a.j[job].h[r] = h; a.j[job].l[r] = l;
    }
}

// ---------------- elementwise kernels ----------------
__global__ void lstm_cell_split(const float* __restrict__ gates, float* __restrict__ c,
                                float* __restrict__ hraw,
                                float* __restrict__ hhi, float* __restrict__ hlo,
                                u32* __restrict__ rstmax)
{
    const int t = blockIdx.x * blockDim.x + threadIdx.x;
    if (t >= CB * CH) return;
    if (rstmax && t < CB) rstmax[t] = 0u;   // smallest key
    const int b = t >> 10, j = t & 1023;
    const float* g = gates + (size_t)b * (4 * CH);
    const float gi = g[j], gf = g[CH + j], gg = g[2 * CH + j], go = g[3 * CH + j];
    const float ig = 1.f / (1.f + __expf(-gi));
    const float fg = 1.f / (1.f + __expf(-gf));
    const float og = 1.f / (1.f + __expf(-go));
    const float cn = fg * c[t] + ig * tanhf(gg);
    c[t] = cn;
    const float h = og * tanhf(cn);
    hraw[t] = h;
    const float hh = tf32r(h);
    hhi[t] = hh;
    hlo[t] = tf32r(h - hh);
}

// max squared row-norm of probs_W
__global__ void wnorms_max(const float* __restrict__ W, float* __restrict__ wmax2)
{
    const int row = blockIdx.x * 8 + (threadIdx.x >> 5);
    const int lane = threadIdx.x & 31;
    if (row >= CV) return;
    const float* w = W + (size_t)row * CH;
    float s = 0.f;
    for (int k = lane; k < CH; k += 32) { float v = w[k]; s += v * v; }
#pragma unroll
    for (int st = 16; st > 0; st >>= 1) s += __shfl_xor_sync(0xffffffff, s, st);
    if (lane == 0) atomicMax((int*)wmax2, __float_as_int(s));
}

// argmax + exact fp32 rescue.
// If logits_bf != null (t<19): mall from rowMaxKey, candidates from bf16 scan with
// widened threshold thr2 = thr - 2^-9*(|mall|+margin) (provably superset).
// Else (t=19): full fp32 scan with online logsumexp.
__global__ void logits_argmax(const float* __restrict__ logits,
                              const __nv_bfloat16* __restrict__ logits_bf,
                              const float* __restrict__ h,
                              const float* __restrict__ W,
                              const float* __restrict__ pb,
                              const float* __restrict__ wmax2,
                              const u32* __restrict__ rowMaxKey,
                              int* __restrict__ tok, float* __restrict__ lp,
                              int want_lp, int mshift)
{
    const int b = blockIdx.x;
    const int tid = threadIdx.x;
    __shared__ float sh[CH];
    __shared__ float smx[256], ssm[256];
    __shared__ int   sidxs[256];

    float nrm = 0.f;
    for (int i = tid; i < CH; i += 256) { float v = h[(size_t)b * CH + i]; sh[i] = v; nrm += v * v; }
    smx[tid] = nrm;
    __syncthreads();
    for (int st = 128; st > 0; st >>= 1) {
        if (tid < st) smx[tid] += smx[tid + st];
        __syncthreads();
    }
    const float hn2 = smx[0];
    __syncthreads();

    float mall, sall = 0.f;
    if (logits_bf) {
        mall = fdec(rowMaxKey[b]);
    } else {
        const float4* row4 = (const float4*)(logits + (size_t)b * CV);
        float m = -3.4e38f, s = 0.f;
        for (int j4 = tid; j4 < CV / 4; j4 += 256) {
            float4 v = row4[j4];
            float xs[4] = {v.x, v.y, v.z, v.w};
#pragma unroll
            for (int c = 0; c < 4; c++) {
                float x = xs[c];
                if (x > m) {
                    if (want_lp) s = s * expf(m - x) + 1.f;
                    m = x;
                } else if (want_lp) {
                    s += expf(x - m);
                }
            }
        }
        smx[tid] = m; ssm[tid] = s;
        __syncthreads();
        for (int st = 128; st > 0; st >>= 1) {
            if (tid < st) {
                float m1 = smx[tid], s1 = ssm[tid];
                float m2 = smx[tid + st], s2 = ssm[tid + st];
                if (m2 > m1) { smx[tid] = m2; ssm[tid] = s2 + s1 * expf(m1 - m2); }
                else         { ssm[tid] = s1 + s2 * expf(m2 - m1); }
            }
            __syncthreads();
        }
        mall = smx[0];
        sall = ssm[0];
        __syncthreads();
    }

    const float margin = ldexpf(sqrtf(hn2 * wmax2[0]), mshift);
    const float thr = mall - margin;

    float bv = -3.4e38f; int bi = 0x7fffffff;
    if (logits_bf) {
        // bf16 storage error <= 2^-9 * |x|; widen threshold accordingly
        const float thr2 = thr - ldexpf(fabsf(mall) + margin, -9);
        const uint4* rb4 = (const uint4*)(logits_bf + (size_t)b * CV);
        for (int j8 = tid; j8 < CV / 8; j8 += 256) {
            uint4 pk = rb4[j8];
            u32 ws[4] = {pk.x, pk.y, pk.z, pk.w};
#pragma unroll
            for (int c = 0; c < 4; c++) {
                float lo = __bfloat162float(__ushort_as_bfloat16((unsigned short)(ws[c] & 0xffff)));
                float hi = __bfloat162float(__ushort_as_bfloat16((unsigned short)(ws[c] >> 16)));
#pragma unroll
                for (int e = 0; e < 2; e++) {
                    float x = e ? hi : lo;
                    if (x >= thr2) {
                        int j = j8 * 8 + c * 2 + e;
                        const float* w = W + (size_t)j * CH;
                        float dot = pb[j];
#pragma unroll 4
                        for (int k = 0; k < CH; k++) dot = fmaf(sh[k], w[k], dot);
                        if (dot > bv || (dot == bv && j < bi)) { bv = dot; bi = j; }
                    }
                }
            }
        }
    } else {
        const float* row = logits + (size_t)b * CV;
        for (int j = tid; j < CV; j += 256) {
            if (row[j] >= thr) {
                const float* w = W + (size_t)j * CH;
                float dot = pb[j];
#pragma unroll 4
                for (int k = 0; k < CH; k++) dot = fmaf(sh[k], w[k], dot);
                if (dot > bv || (dot == bv && j < bi)) { bv = dot; bi = j; }
            }
        }
    }
    smx[tid] = bv; sidxs[tid] = bi;
    __syncthreads();
    for (int st = 128; st > 0; st >>= 1) {
        if (tid < st) {
            float v2 = smx[tid + st]; int i2 = sidxs[tid + st];
            if (v2 > smx[tid] || (v2 == smx[tid] && i2 < sidxs[tid])) { smx[tid] = v2; sidxs[tid] = i2; }
        }
        __syncthreads();
    }
    if (tid == 0) {
        tok[b] = sidxs[0];
        if (want_lp) lp[b] = smx[0] - (mall + logf(sall));
    }
}

// ---------------- hinge loss / accuracy reductions ----------------
__global__ void score_rows(const float* __restrict__ ts, const float* __restrict__ ds,
                           const float* __restrict__ lp,
                           float* __restrict__ rowloss, float* __restrict__ rowcorr)
{
    const int i = blockIdx.x;
    const float* trow = ts + (size_t)i * CB;
    const float* dr0 = ds + 0ULL * CB * CB + (size_t)i * CB;
    const float* dr1 = ds + 1ULL * CB * CB + (size_t)i * CB;
    const float* dr2 = ds + 2ULL * CB * CB + (size_t)i * CB;
    const float* dr3 = ds + 3ULL * CB * CB + (size_t)i * CB;

    float ls = 0.f, et = 0.f, e0 = 0.f, e1 = 0.f, e2 = 0.f, e3 = 0.f;
    for (int j = threadIdx.x; j < CB; j += 256) {
        const float t  = trow[j];
        const float a0 = dr0[j], a1 = dr1[j], a2 = dr2[j], a3 = dr3[j];
        float h = fmaxf(0.f, 1.f - t + a0) + fmaxf(0.f, 1.f - t + a1)
                + fmaxf(0.f, 1.f - t + a2) + fmaxf(0.f, 1.f - t + a3);
        ls += h * lp[j];
        et += expf(t); e0 += expf(a0); e1 += expf(a1); e2 += expf(a2); e3 += expf(a3);
    }
    __shared__ float red[6][256];
    red[0][threadIdx.x] = ls; red[1][threadIdx.x] = et;
    red[2][threadIdx.x] = e0; red[3][threadIdx.x] = e1;
    red[4][threadIdx.x] = e2; red[5][threadIdx.x] = e3;
    __syncthreads();
    for (int st = 128; st > 0; st >>= 1) {
        if (threadIdx.x < st)
#pragma unroll
            for (int q = 0; q < 6; q++) red[q][threadIdx.x] += red[q][threadIdx.x + st];
        __syncthreads();
    }
    if (threadIdx.x == 0) {
        rowloss[i] = red[0][0];
        const float tp = red[1][0] / (float)CB;
        const float mx = fmaxf(fmaxf(red[2][0], red[3][0]), fmaxf(red[4][0], red[5][0])) / (float)CB;
        rowcorr[i] = (tp >= mx) ? 1.f : 0.f;
    }
}

__global__ void final_reduce(const float* __restrict__ rowloss,
                             const float* __restrict__ rowcorr, float* __restrict__ out)
{
    __shared__ float s1[256], s2[256];
    float a = 0.f, b = 0.f;
    for (int i = threadIdx.x; i < CB; i += 256) { a += rowloss[i]; b += rowcorr[i]; }
    s1[threadIdx.x] = a; s2[threadIdx.x] = b;
    __syncthreads();
    for (int st = 128; st > 0; st >>= 1) {
        if (threadIdx.x < st) { s1[threadIdx.x] += s1[threadIdx.x + st]; s2[threadIdx.x] += s2[threadIdx.x + st]; }
        __syncthreads();
    }
    if (threadIdx.x == 0) {
        out[0] = -s1[0] / (float)((size_t)CB * CB);
        out[1] =  s2[0] / (float)CB;
    }
}

// ---------------------------------------------------------------------------
extern "C" void kernel_launch(void* const* d_in, const int* in_sizes, int n_in,
                              void* d_out, int out_size)
{
    (void)in_sizes; (void)n_in; (void)out_size;
    const float* target   = (const float*)d_in[0];
    const float* distract = (const float*)d_in[1];
    const int*   sidx     = (const int*)d_in[2];
    const float* emb_s   = (const float*)d_in[4];
    const float* Wih_s   = (const float*)d_in[5];
    const float* Whh_s   = (const float*)d_in[6];
    const float* bih_s   = (const float*)d_in[7];
    const float* bhh_s   = (const float*)d_in[8];
    const float* aff_s_W = (const float*)d_in[9];
    const float* aff_s_b = (const float*)d_in[10];
    const float* probs_W = (const float*)d_in[11];
    const float* probs_b = (const float*)d_in[12];
    const float* emb_r   = (const float*)d_in[13];
    const float* Wih_r   = (const float*)d_in[14];
    const float* Whh_r   = (const float*)d_in[15];
    const float* bih_r   = (const float*)d_in[16];
    const float* bhh_r   = (const float*)d_in[17];
    const float* aff_r_W = (const float*)d_in[18];
    const float* aff_r_b = (const float*)d_in[19];
    float* out = (float*)d_out;

    static cudaStream_t s2 = nullptr;
    static cudaEvent_t evFork = nullptr, evJoin = nullptr, evTok[CL];
    if (!s2) {
        cudaStreamCreateWithFlags(&s2, cudaStreamNonBlocking);
        cudaEventCreateWithFlags(&evFork, cudaEventDisableTiming);
        cudaEventCreateWithFlags(&evJoin, cudaEventDisableTiming);
        for (int t = 0; t < CL; t++) cudaEventCreateWithFlags(&evTok[t], cudaEventDisableTiming);
    }

    cudaFuncSetAttribute(tmma_nt<3, 2>, cudaFuncAttributeMaxDynamicSharedMemorySize, SMEM_G);
    cudaFuncSetAttribute(tmma_nt<1, 4>, cudaFuncAttributeMaxDynamicSharedMemorySize, SMEM_G);

#define SYM(T, p, s) T* p; cudaGetSymbolAddress((void**)&p, s)
    SYM(float, pwh, g_pw_h); SYM(float, pwl, g_pw_l);
    SYM(float, embsh, g_embs_h); SYM(float, embsl, g_embs_l);
    SYM(float, embrh, g_embr_h); SYM(float, embrl, g_embr_l);
    SYM(float, wihsh, g_wihs_h); SYM(float, wihsl, g_wihs_l);
    SYM(float, whhsh, g_whhs_h); SYM(float, whhsl, g_whhs_l);
    SYM(float, wihrh, g_wihr_h); SYM(float, wihrl, g_wihr_l);
    SYM(float, whhrh, g_whhr_h); SYM(float, whhrl, g_whhr_l);
    SYM(float, affsh, g_affs_h); SYM(float, affsl, g_affs_l);
    SYM(float, affrh, g_affr_h); SYM(float, affrl, g_affr_l);
    SYM(float, tgth, g_tgt_h);   SYM(float, tgtl, g_tgt_l);
    SYM(float, dsth, g_dst_h);   SYM(float, dstl, g_dst_l);
    SYM(float, rh, g_r_h);       SYM(float, rl, g_r_l);
    SYM(float, hsh, g_hs_h);     SYM(float, hsl, g_hs_l);
    SYM(float, hrh, g_hr_h);     SYM(float, hrl, g_hr_l);
    SYM(float, p_logits, g_logits);
    SYM(__nv_bfloat16, p_logits_bf, g_logits_bf);
    SYM(float, p_gates, g_gates); SYM(float, p_gates_r, g_gates_r);
    SYM(float, p_hs, g_hs); SYM(float, p_hr, g_hr); SYM(float, p_cs, g_cs); SYM(float, p_cr, g_cr);
    SYM(float, p_lp, g_lp); SYM(float, p_r, g_r); SYM(float, p_ts, g_ts); SYM(float, p_ds, g_ds);
    SYM(float, p_rowloss, g_rowloss); SYM(float, p_rowcorr, g_rowcorr);
    SYM(float, p_wmax2, g_wmax2);
    SYM(u32, p_rmk, g_rowmaxk);
    SYM(int, p_msg, g_msg);
#undef SYM

    constexpr size_t N4_PW  = (size_t)CV * CH / 4;
    constexpr size_t N4_EMB = (size_t)CV * CE / 4;
    constexpr size_t N4_WIH = (size_t)CH * CE;       // 4*CH*CE/4
    constexpr size_t N4_WHH = (size_t)CH * CH;       // 4*CH*CH/4
    constexpr size_t N4_AFF = (size_t)CH * CF / 4;
    constexpr size_t N4_TGT = (size_t)CB * CF / 4;
    constexpr size_t N4_DST = (size_t)CD * CB * CF / 4;
    constexpr size_t N4_Z   = (size_t)CB * CH / 4;

    // fork s2 immediately (receiver-side prepass overlaps sender work)
    cudaEventRecord(evFork, 0);
    cudaStreamWaitEvent(s2, evFork, 0);

    // prep_main (stream 0): pw, wihs, whhs, affs, tgt, embs + zero cs
    {
        PrepArgs a{};
        a.j[0] = {(const float4*)probs_W, (float4*)pwh,   (float4*)pwl};    a.jsz[0] = N4_PW;
        a.j[1] = {(const float4*)Wih_s,   (float4*)wihsh, (float4*)wihsl};  a.jsz[1] = N4_WIH;
        a.j[2] = {(const float4*)Whh_s,   (float4*)whhsh, (float4*)whhsl};  a.jsz[2] = N4_WHH;
        a.j[3] = {(const float4*)aff_s_W, (float4*)affsh, (float4*)affsl};  a.jsz[3] = N4_AFF;
        a.j[4] = {(const float4*)target,  (float4*)tgth,  (float4*)tgtl};   a.jsz[4] = N4_TGT;
        a.j[5] = {(const float4*)emb_s,   (float4*)embsh, (float4*)embsl};  a.jsz[5] = N4_EMB;
        a.nj = 6;
        a.z[0] = (float4*)p_cs; a.nz = 1; a.zsz = N4_Z;
        a.wmax2 = p_wmax2; a.initw = 1;
        a.split_tot = N4_PW + N4_WIH + N4_WHH + N4_AFF + N4_TGT + N4_EMB;
        a.tot = a.split_tot + 1 * N4_Z;
        prep_all<<<2048, 256>>>(a);
    }
    // prep_recv (stream s2): wihr, whhr, affr, embr, dst + zero cr/hrh/hrl
    {
        PrepArgs a{};
        a.j[0] = {(const float4*)Wih_r,   (float4*)wihrh, (float4*)wihrl};  a.jsz[0] = N4_WIH;
        a.j[1] = {(const float4*)Whh_r,   (float4*)whhrh, (float4*)whhrl};  a.jsz[1] = N4_WHH;
        a.j[2] = {(const float4*)aff_r_W, (float4*)affrh, (float4*)affrl};  a.jsz[2] = N4_AFF;
        a.j[3] = {(const float4*)emb_r,   (float4*)embrh, (float4*)embrl};  a.jsz[3] = N4_EMB;
        a.j[4] = {(const float4*)distract,(float4*)dsth,  (float4*)dstl};   a.jsz[4] = N4_DST;
        a.nj = 5;
        a.z[0] = (float4*)p_cr; a.z[1] = (float4*)hrh; a.z[2] = (float4*)hrl;
        a.nz = 3; a.zsz = N4_Z;
        a.wmax2 = p_wmax2; a.initw = 0;
        a.split_tot = N4_WIH + N4_WHH + N4_AFF + N4_EMB + N4_DST;
        a.tot = a.split_tot + 3 * N4_Z;
        prep_all<<<2048, 256, 0, s2>>>(a);
    }

    wnorms_max<<<(CV + 7) / 8, 256>>>(probs_W, p_wmax2);

    // h0 = target @ aff_s_W^T + aff_s_b  (split fused into epilogue)
    tmma_nt<3, 2><<<dim3(CH / BN, CB / BM), 256, SMEM_G>>>(CB, CH,
        tgth, tgtl, CF, nullptr, nullptr, nullptr, nullptr, 0,
        affsh, affsl, nullptr, nullptr, aff_s_b, nullptr,
        p_hs, nullptr, nullptr, hsh, hsl);

    // ---- sender (stream 0) ----
    for (int t = 0; t < CL; t++) {
        const int* tokidx = (t == 0) ? nullptr : (p_msg + (t - 1) * CB);
        const int* stok   = (t == 0) ? sidx : nullptr;
        // gates = emb_s[tok] @ Wih^T + hs @ Whh^T + biases  (gather fused)
        tmma_nt<3, 2><<<dim3(4 * CH / BN, CB / BM), 256, SMEM_G>>>(CB, 4 * CH,
            embsh, embsl, CE, tokidx, stok, hsh, hsl, CH,
            wihsh, wihsl, whhsh, whhsl, bih_s, bhh_s,
            p_gates, nullptr, nullptr, nullptr, nullptr);
        lstm_cell_split<<<(CB * CH) / 256, 256>>>(p_gates, p_cs, p_hs, hsh, hsl, p_rmk);
        const int last = (t == CL - 1);
        tmma_nt<1, 4><<<dim3((CV + BN - 1) / BN, CB / BM), 256, SMEM_G>>>(CB, CV,
            hsh, nullptr, CH, nullptr, nullptr, nullptr, nullptr, 0,
            pwh, nullptr, nullptr, nullptr, probs_b, nullptr,
            last ? p_logits : nullptr, last ? nullptr : p_logits_bf,
            last ? nullptr : p_rmk, nullptr, nullptr);
        logits_argmax<<<CB, 256>>>(p_logits, last ? nullptr : p_logits_bf,
                                   p_hs, probs_W, probs_b, p_wmax2, p_rmk,
                                   p_msg + t * CB, p_lp, last, -8);
        cudaEventRecord(evTok[t], 0);
    }

    // ---- receiver (stream s2, overlapped; gather fused) ----
    for (int t = 0; t < CL; t++) {
        cudaStreamWaitEvent(s2, evTok[t], 0);
        tmma_nt<3, 2><<<dim3(4 * CH / BN, CB / BM), 256, SMEM_G, s2>>>(CB, 4 * CH,
            embrh, embrl, CE, p_msg + t * CB, nullptr, hrh, hrl, CH,
            wihrh, wihrl, whhrh, whhrl, bih_r, bhh_r,
            p_gates_r, nullptr, nullptr, nullptr, nullptr);
        lstm_cell_split<<<(CB * CH) / 256, 256, 0, s2>>>(p_gates_r, p_cr, p_hr, hrh, hrl, nullptr);
    }
    cudaEventRecord(evJoin, s2);
    cudaStreamWaitEvent(0, evJoin, 0);

    // r = hr @ aff_r_W^T + aff_r_b  (split fused into epilogue)
    tmma_nt<3, 2><<<dim3(CF / BN, CB / BM), 256, SMEM_G>>>(CB, CF,
        hrh, hrl, CH, nullptr, nullptr, nullptr, nullptr, 0,
        affrh, affrl, nullptr, nullptr, aff_r_b, nullptr,
        p_r, nullptr, nullptr, rh, rl);

    // ts = target @ r^T ; ds = distractors @ r^T
    tmma_nt<3, 2><<<dim3(CB / BN, CB / BM), 256, SMEM_G>>>(CB, CB,
        tgth, tgtl, CF, nullptr, nullptr, nullptr, nullptr, 0,
        rh, rl, nullptr, nullptr, nullptr, nullptr,
        p_ts, nullptr, nullptr, nullptr, nullptr);
    tmma_nt<3, 2><<<dim3(CB / BN, (CD * CB) / BM), 256, SMEM_G>>>(CD * CB, CB,
        dsth, dstl, CF, nullptr, nullptr, nullptr, nullptr, 0,
        rh, rl, nullptr, nullptr, nullptr, nullptr,
        p_ds, nullptr, nullptr, nullptr, nullptr);

    score_rows<<<CB, 256>>>(p_ts, p_ds, p_lp, p_rowloss, p_rowcorr);
    final_reduce<<<1, 256>>>(p_rowloss, p_rowcorr, out);
}